// round 1
// baseline (speedup 1.0000x reference)
#include <cuda_runtime.h>
#include <math.h>

#define BB 2
#define NN 384
#define CC 1024
#define HREPN 256
#define GHID 256
#define NHEADS 4
#define TOPKK 8
#define KX 1028            // C + 4 geometry features
#define MAXDEG 400         // max in-degree = 384 + self loop = 385

// ---------------- scratch (device globals; no allocation allowed) ------------
__device__ __align__(16) float g_xbuf[BB*NN*KX];
__device__ __align__(16) float g_p1 [BB*NN*HREPN];
__device__ __align__(16) float g_p2 [BB*NN*HREPN];
__device__ __align__(16) float g_xw1[BB*NN*NHEADS*GHID];
__device__ float g_as1[BB*NN*NHEADS];
__device__ float g_ad1[BB*NN*NHEADS];
__device__ int   g_nbr[BB*NN*TOPKK];
__device__ int   g_srcl[BB*NN*MAXDEG];
__device__ int   g_deg [BB*NN];
__device__ __align__(16) float g_h1 [BB*NN*NHEADS*GHID];
__device__ float g_xw2[BB*NN*2];
__device__ float g_as2[BB*NN];
__device__ float g_ad2[BB*NN];

// ---------------- build x = [feats | normalized geom] ------------------------
__global__ void k_xbuf(const float* __restrict__ feats, const float* __restrict__ boxes) {
    int idx = blockIdx.x * blockDim.x + threadIdx.x;
    const int total = BB*NN*KX;
    if (idx >= total) return;
    int c  = idx % KX;
    int bn = idx / KX;
    if (c < CC) {
        g_xbuf[idx] = feats[bn*CC + c];
    } else {
        const float* bx = boxes + bn*4;
        float x0 = bx[0] * (1.0f/800.0f);
        float y0 = bx[1] * (1.0f/800.0f);
        float x1 = bx[2] * (1.0f/800.0f);
        float y1 = bx[3] * (1.0f/800.0f);
        int d = c - CC;
        float v = (d == 0) ? x0 : (d == 1) ? y0 : (d == 2) ? (x1 - x0) : (y1 - y0);
        g_xbuf[idx] = v;
    }
}

// ---------------- fused SGEMM dispatcher (p1, p2, xw1 in ONE launch) ---------
// 64x64 tiles, 256 threads, 4x4 per-thread register blocking, k-tile = 16.
// blocks: p1 -> 48 (4x6x2), p2 -> 48, xw1 -> 192 (16x6x2). total 288.
__global__ __launch_bounds__(256) void k_gemms(
    const float* __restrict__ feats,
    const float* __restrict__ fc1_w,
    const float* __restrict__ gat1_w)
{
    __shared__ float As[64][20];   // [row][k], pad 20 keeps 16B alignment for float4 STS
    __shared__ float Bs[16][64];   // [k][col]

    int bid = blockIdx.x;
    int sel, bx, by, b;
    if (bid < 96) {
        sel = bid / 48;
        int r = bid % 48;
        b  = r / 24; r %= 24;
        by = r / 4;  bx = r % 4;
    } else {
        sel = 2;
        int r = bid - 96;
        b  = r / 96; r %= 96;
        by = r / 16; bx = r % 16;
    }

    const float* A; const float* Bm; float* Cm;
    int K, lda, ldb, Nc;
    if (sel == 0) { A = feats + b*NN*CC; Bm = fc1_w;               Cm = g_p1  + b*NN*HREPN; K = 1024; lda = 1024; ldb = 256;  Nc = 256;  }
    else if (sel == 1) { A = feats + b*NN*CC; Bm = fc1_w + 1024*256; Cm = g_p2 + b*NN*HREPN; K = 1024; lda = 1024; ldb = 256;  Nc = 256;  }
    else { A = g_xbuf + b*NN*KX; Bm = gat1_w;                      Cm = g_xw1 + b*NN*1024;  K = 1028; lda = 1028; ldb = 1024; Nc = 1024; }

    int tid = threadIdx.x;
    int tx = tid % 16, ty = tid / 16;
    int row0 = by * 64, col0 = bx * 64;

    float acc[4][4];
    #pragma unroll
    for (int i = 0; i < 4; i++)
        #pragma unroll
        for (int j = 0; j < 4; j++) acc[i][j] = 0.f;

    // A-load mapping: r = tid/4 (row 0..63), kq = tid%4 (float4 slot)
    int ar = tid >> 2, akq = tid & 3;
    // B-load mapping: c = tid%64, kb = tid/64
    int bc = tid & 63, bkb = tid >> 6;

    for (int k0 = 0; k0 < K; k0 += 16) {
        // load A tile 64x16 (one float4 per thread)
        {
            int kg = k0 + akq*4;
            float4 v;
            if (kg + 3 < K) {
                v = *(const float4*)&A[(row0 + ar)*lda + kg];
            } else {
                v = make_float4(0.f, 0.f, 0.f, 0.f);
            }
            *(float4*)&As[ar][akq*4] = v;
        }
        // load B tile 16x64 (4 scalars per thread)
        #pragma unroll
        for (int it = 0; it < 4; it++) {
            int kk = bkb + it*4;
            int kg = k0 + kk;
            Bs[kk][bc] = (kg < K) ? Bm[kg*ldb + col0 + bc] : 0.f;
        }
        __syncthreads();
        #pragma unroll
        for (int kk = 0; kk < 16; kk++) {
            float a0 = As[ty*4+0][kk];
            float a1 = As[ty*4+1][kk];
            float a2 = As[ty*4+2][kk];
            float a3 = As[ty*4+3][kk];
            float4 bq = *(const float4*)&Bs[kk][tx*4];
            acc[0][0] = fmaf(a0, bq.x, acc[0][0]); acc[0][1] = fmaf(a0, bq.y, acc[0][1]);
            acc[0][2] = fmaf(a0, bq.z, acc[0][2]); acc[0][3] = fmaf(a0, bq.w, acc[0][3]);
            acc[1][0] = fmaf(a1, bq.x, acc[1][0]); acc[1][1] = fmaf(a1, bq.y, acc[1][1]);
            acc[1][2] = fmaf(a1, bq.z, acc[1][2]); acc[1][3] = fmaf(a1, bq.w, acc[1][3]);
            acc[2][0] = fmaf(a2, bq.x, acc[2][0]); acc[2][1] = fmaf(a2, bq.y, acc[2][1]);
            acc[2][2] = fmaf(a2, bq.z, acc[2][2]); acc[2][3] = fmaf(a2, bq.w, acc[2][3]);
            acc[3][0] = fmaf(a3, bq.x, acc[3][0]); acc[3][1] = fmaf(a3, bq.y, acc[3][1]);
            acc[3][2] = fmaf(a3, bq.z, acc[3][2]); acc[3][3] = fmaf(a3, bq.w, acc[3][3]);
        }
        __syncthreads();
    }

    #pragma unroll
    for (int i = 0; i < 4; i++) {
        int r = row0 + ty*4 + i;
        #pragma unroll
        for (int j = 0; j < 4; j++) {
            Cm[r*Nc + col0 + tx*4 + j] = acc[i][j];
        }
    }
}

// ---------------- fused relation scores + top-8 neighbors --------------------
__global__ __launch_bounds__(256) void k_rel_topk(
    const float* __restrict__ boxes,
    const float* __restrict__ fc1_w,
    const float* __restrict__ fc1_b,
    const float* __restrict__ fc2_w)
{
    int bn = blockIdx.x;
    int b = bn / NN, i = bn % NN;
    __shared__ float sp1[256], sw2[256], swg[4][256], srow[NN], sbx[4];
    __shared__ float sval[256];
    __shared__ int   sidx[256];
    int tid = threadIdx.x;

    sp1[tid] = g_p1[bn*256 + tid] + fc1_b[tid];
    sw2[tid] = fc2_w[tid];
    #pragma unroll
    for (int d = 0; d < 4; d++) swg[d][tid] = fc1_w[(2048 + d)*256 + tid];
    if (tid < 4) sbx[tid] = boxes[bn*4 + tid];
    __syncthreads();

    int warp = tid >> 5, lane = tid & 31;
    const float* p2b = g_p2 + b*NN*256;
    const float* bxb = boxes + b*NN*4;

    for (int j = warp; j < NN; j += 8) {
        float a0 = fabsf(sbx[0] - bxb[j*4+0]);
        float a1 = fabsf(sbx[1] - bxb[j*4+1]);
        float a2 = fabsf(sbx[2] - bxb[j*4+2]);
        float a3 = fabsf(sbx[3] - bxb[j*4+3]);
        const float* p2r = p2b + j*256;
        float sum = 0.f;
        #pragma unroll
        for (int kk = 0; kk < 8; kk++) {
            int k = lane + kk*32;
            float t = sp1[k] + p2r[k];
            t = fmaf(a0, swg[0][k], t);
            t = fmaf(a1, swg[1][k], t);
            t = fmaf(a2, swg[2][k], t);
            t = fmaf(a3, swg[3][k], t);
            t = fmaxf(t, 0.f);
            sum = fmaf(t, sw2[k], sum);
        }
        #pragma unroll
        for (int o = 16; o; o >>= 1) sum += __shfl_down_sync(0xffffffffu, sum, o);
        if (lane == 0) srow[j] = sum;   // + fc2_b is a constant shift: irrelevant for top-k
    }
    __syncthreads();
    if (tid == 0) srow[i] -= 1e6f;
    __syncthreads();

    // iterative argmax (value desc, index asc on ties = JAX top_k order)
    for (int sel = 0; sel < TOPKK; sel++) {
        float bv = -3.4e38f; int bi = 0x7fffffff;
        for (int j = tid; j < NN; j += 256) {
            float v = srow[j];
            if (v > bv || (v == bv && j < bi)) { bv = v; bi = j; }
        }
        sval[tid] = bv; sidx[tid] = bi;
        __syncthreads();
        for (int s = 128; s; s >>= 1) {
            if (tid < s) {
                float v2 = sval[tid + s]; int i2 = sidx[tid + s];
                if (v2 > sval[tid] || (v2 == sval[tid] && i2 < sidx[tid])) {
                    sval[tid] = v2; sidx[tid] = i2;
                }
            }
            __syncthreads();
        }
        if (tid == 0) {
            g_nbr[bn*TOPKK + sel] = sidx[0];
            srow[sidx[0]] = -3.4e38f;
        }
        __syncthreads();
    }
}

// ---------------- GAT1 per-node attention coefficients -----------------------
__global__ __launch_bounds__(128) void k_asad(
    const float* __restrict__ att_src, const float* __restrict__ att_dst)
{
    int bn = blockIdx.x;
    int warp = threadIdx.x >> 5, lane = threadIdx.x & 31;   // warp == head
    const float* xw = g_xw1 + bn*1024 + warp*256;
    float s1 = 0.f, s2 = 0.f;
    #pragma unroll
    for (int it = 0; it < 8; it++) {
        int c = lane + it*32;
        float v = xw[c];
        s1 = fmaf(v, att_src[warp*256 + c], s1);
        s2 = fmaf(v, att_dst[warp*256 + c], s2);
    }
    #pragma unroll
    for (int o = 16; o; o >>= 1) {
        s1 += __shfl_down_sync(0xffffffffu, s1, o);
        s2 += __shfl_down_sync(0xffffffffu, s2, o);
    }
    if (lane == 0) { g_as1[bn*4 + warp] = s1; g_ad1[bn*4 + warp] = s2; }
}

// ---------------- deterministic incoming-edge lists --------------------------
__global__ void k_build() {
    int t = blockIdx.x * blockDim.x + threadIdx.x;
    if (t >= BB*NN) return;
    int b = t / NN, tt = t % NN;
    const int* nb = g_nbr + b*NN*TOPKK;
    int* dst = g_srcl + t*MAXDEG;
    int cnt = 0;
    for (int i = 0; i < NN; i++) {
        #pragma unroll
        for (int k = 0; k < TOPKK; k++)
            if (nb[i*TOPKK + k] == tt) dst[cnt++] = i;
    }
    dst[cnt++] = tt;   // self loop
    g_deg[t] = cnt;
}

// ---------------- GAT layer 1: softmax + aggregate + bias + relu -------------
__global__ __launch_bounds__(256) void k_gat1(const float* __restrict__ gat1_b) {
    int bn = blockIdx.x; int b = bn / NN;
    __shared__ int   ssrc[MAXDEG];
    __shared__ float sal[NHEADS][MAXDEG];
    int tid = threadIdx.x;
    int deg = g_deg[bn];
    for (int s = tid; s < deg; s += 256) ssrc[s] = g_srcl[bn*MAXDEG + s];
    __syncthreads();

    int warp = tid >> 5, lane = tid & 31;
    if (warp < NHEADS) {
        int h = warp;
        float adv = g_ad1[bn*4 + h];
        float m = -3.4e38f;
        for (int s = lane; s < deg; s += 32) {
            float e = g_as1[(b*NN + ssrc[s])*4 + h] + adv;
            e = (e >= 0.f) ? e : 0.2f*e;
            sal[h][s] = e;
            m = fmaxf(m, e);
        }
        #pragma unroll
        for (int o = 16; o; o >>= 1) m = fmaxf(m, __shfl_xor_sync(0xffffffffu, m, o));
        float sum = 0.f;
        for (int s = lane; s < deg; s += 32) {
            float ex = expf(sal[h][s] - m);
            sal[h][s] = ex;
            sum += ex;
        }
        #pragma unroll
        for (int o = 16; o; o >>= 1) sum += __shfl_xor_sync(0xffffffffu, sum, o);
        float inv = 1.f / fmaxf(sum, 1e-16f);
        for (int s = lane; s < deg; s += 32) sal[h][s] *= inv;
    }
    __syncthreads();

    const float* xwb = g_xw1 + b*NN*1024;
    #pragma unroll
    for (int h = 0; h < NHEADS; h++) {
        float acc0 = 0.f, acc1 = 0.f, acc2 = 0.f, acc3 = 0.f;
        int s = 0;
        for (; s + 3 < deg; s += 4) {
            acc0 = fmaf(xwb[ssrc[s+0]*1024 + h*256 + tid], sal[h][s+0], acc0);
            acc1 = fmaf(xwb[ssrc[s+1]*1024 + h*256 + tid], sal[h][s+1], acc1);
            acc2 = fmaf(xwb[ssrc[s+2]*1024 + h*256 + tid], sal[h][s+2], acc2);
            acc3 = fmaf(xwb[ssrc[s+3]*1024 + h*256 + tid], sal[h][s+3], acc3);
        }
        for (; s < deg; s++)
            acc0 = fmaf(xwb[ssrc[s]*1024 + h*256 + tid], sal[h][s], acc0);
        float o = (acc0 + acc1) + (acc2 + acc3) + gat1_b[h*256 + tid];
        g_h1[bn*1024 + h*256 + tid] = fmaxf(o, 0.f);
    }
}

// ---------------- GAT2 projection + coefficients ------------------------------
__global__ __launch_bounds__(64) void k_xw2(
    const float* __restrict__ gat2_w,
    const float* __restrict__ att_src2,
    const float* __restrict__ att_dst2)
{
    int bn = blockIdx.x;
    __shared__ float sx[2];
    int warp = threadIdx.x >> 5, lane = threadIdx.x & 31;  // warp == output channel
    const float* h1 = g_h1 + bn*1024;
    float s = 0.f;
    #pragma unroll
    for (int it = 0; it < 32; it++) {
        int k = lane + it*32;
        s = fmaf(h1[k], gat2_w[k*2 + warp], s);
    }
    #pragma unroll
    for (int o = 16; o; o >>= 1) s += __shfl_down_sync(0xffffffffu, s, o);
    if (lane == 0) { g_xw2[bn*2 + warp] = s; sx[warp] = s; }
    __syncthreads();
    if (threadIdx.x == 0) {
        g_as2[bn] = sx[0]*att_src2[0] + sx[1]*att_src2[1];
        g_ad2[bn] = sx[0]*att_dst2[0] + sx[1]*att_dst2[1];
    }
}

// ---------------- GAT layer 2: softmax + aggregate -> logits -----------------
__global__ __launch_bounds__(32) void k_gat2(const float* __restrict__ gat2_b,
                                             float* __restrict__ out)
{
    int bn = blockIdx.x; int b = bn / NN;
    __shared__ float sal[MAXDEG];
    __shared__ int   ssrc[MAXDEG];
    int lane = threadIdx.x;
    int deg = g_deg[bn];
    for (int s = lane; s < deg; s += 32) ssrc[s] = g_srcl[bn*MAXDEG + s];
    __syncwarp();
    float adv = g_ad2[bn];
    float m = -3.4e38f;
    for (int s = lane; s < deg; s += 32) {
        float e = g_as2[b*NN + ssrc[s]] + adv;
        e = (e >= 0.f) ? e : 0.2f*e;
        sal[s] = e;
        m = fmaxf(m, e);
    }
    #pragma unroll
    for (int o = 16; o; o >>= 1) m = fmaxf(m, __shfl_xor_sync(0xffffffffu, m, o));
    float sum = 0.f;
    for (int s = lane; s < deg; s += 32) {
        float ex = expf(sal[s] - m);
        sal[s] = ex;
        sum += ex;
    }
    #pragma unroll
    for (int o = 16; o; o >>= 1) sum += __shfl_xor_sync(0xffffffffu, sum, o);
    float inv = 1.f / fmaxf(sum, 1e-16f);
    __syncwarp();
    if (lane < 2) {
        float acc = 0.f;
        for (int s = 0; s < deg; s++)
            acc = fmaf(g_xw2[(b*NN + ssrc[s])*2 + lane], sal[s]*inv, acc);
        out[bn*2 + lane] = acc + gat2_b[lane];
    }
}

// ---------------- launch ------------------------------------------------------
extern "C" void kernel_launch(void* const* d_in, const int* in_sizes, int n_in,
                              void* d_out, int out_size)
{
    const float* feats   = (const float*)d_in[0];
    const float* boxes   = (const float*)d_in[1];
    const float* fc1_w   = (const float*)d_in[2];
    const float* fc1_b   = (const float*)d_in[3];
    const float* fc2_w   = (const float*)d_in[4];
    // d_in[5] = fc2_b : constant shift, not needed for top-k
    const float* gat1_w  = (const float*)d_in[6];
    const float* g1as    = (const float*)d_in[7];
    const float* g1ad    = (const float*)d_in[8];
    const float* gat1_b  = (const float*)d_in[9];
    const float* gat2_w  = (const float*)d_in[10];
    const float* g2as    = (const float*)d_in[11];
    const float* g2ad    = (const float*)d_in[12];
    const float* gat2_b  = (const float*)d_in[13];
    float* out = (float*)d_out;

    const int total_x = BB*NN*KX;
    k_xbuf<<<(total_x + 255)/256, 256>>>(feats, boxes);
    k_gemms<<<288, 256>>>(feats, fc1_w, gat1_w);
    k_rel_topk<<<BB*NN, 256>>>(boxes, fc1_w, fc1_b, fc2_w);
    k_asad<<<BB*NN, 128>>>(g1as, g1ad);
    k_build<<<(BB*NN + 255)/256, 256>>>();
    k_gat1<<<BB*NN, 256>>>(gat1_b);
    k_xw2<<<BB*NN, 64>>>(gat2_w, g2as, g2ad);
    k_gat2<<<BB*NN, 32>>>(gat2_b, out);
    (void)in_sizes; (void)n_in; (void)out_size;
}

// round 2
// speedup vs baseline: 1.8796x; 1.8796x over previous
#include <cuda_runtime.h>
#include <math.h>

#define BB 2
#define NN 384
#define CC 1024
#define HREPN 256
#define GHID 256
#define NHEADS 4
#define TOPKK 8
#define MAXDEG 400

typedef unsigned long long ull;

// ---------------- scratch (device globals; no allocation allowed) ------------
__device__ __align__(16) float g_p1 [BB*NN*HREPN];
__device__ __align__(16) float g_p2 [BB*NN*HREPN];
__device__ __align__(16) float g_xw1[BB*NN*NHEADS*GHID];
__device__ float g_as1[BB*NN*NHEADS];
__device__ float g_ad1[BB*NN*NHEADS];
__device__ int   g_nbr[BB*NN*TOPKK];
__device__ int   g_srcl[BB*NN*MAXDEG];
__device__ int   g_deg [BB*NN];
__device__ __align__(16) float g_h1 [BB*NN*NHEADS*GHID];
__device__ float g_xw2[BB*NN*2];
__device__ float g_as2[BB*NN];
__device__ float g_ad2[BB*NN];

__device__ __forceinline__ void ffma2(ull &d, ull a, ull b) {
    asm("fma.rn.f32x2 %0, %1, %2, %0;" : "+l"(d) : "l"(a), "l"(b));
}

// ---------------- fused SGEMM dispatcher (p1, p2, xw1 in ONE launch) ---------
// 128x64 tiles, 256 threads, 8x4 per-thread blocking with k-paired f32x2 FMA.
// sel 0 (48 blocks): p1/p2 = feats @ fc1_w[0:2048]   (M=384, N=512, K=1024)
// sel 1 (96 blocks): xw1  = feats @ gat1_w[0:1024] + geom epilogue (N=1024)
__global__ __launch_bounds__(256) void k_gemms(
    const float* __restrict__ feats,
    const float* __restrict__ fc1_w,
    const float* __restrict__ gat1_w,
    const float* __restrict__ boxes)
{
    __shared__ float As[128*20];   // [row][k], ld=20 (float4-aligned stores)
    __shared__ float Bs[64*18];    // [col][k], ld=18 (conflict-free LDS.64)
    __shared__ float Wg4[4*64];

    int tid = threadIdx.x;
    int bid = blockIdx.x;
    int sel, b, by, bx;
    if (bid < 48) { sel = 0; b = bid / 24; int r = bid % 24; by = r / 8;  bx = r % 8;  }
    else { sel = 1; int r = bid - 48; b = r / 48; r %= 48;   by = r / 16; bx = r % 16; }

    int row0 = by * 128, col0 = bx * 64;

    const float* A = feats + b*NN*CC;
    const float* Bm; float* Cm;
    int ldb, Nc, dcol0;
    if (sel == 0) {
        ldb = 256; Nc = 256;
        if (col0 < 256) { Bm = fc1_w;            Cm = g_p1 + b*NN*256; dcol0 = col0; }
        else            { Bm = fc1_w + 1024*256; Cm = g_p2 + b*NN*256; dcol0 = col0 - 256; }
    } else {
        ldb = 1024; Nc = 1024; Bm = gat1_w; Cm = g_xw1 + b*NN*1024; dcol0 = col0;
        int d = tid >> 6, c = tid & 63;
        Wg4[d*64 + c] = gat1_w[(1024 + d)*1024 + col0 + c];
    }

    int tx = tid & 15, ty = tid >> 4;
    ull acc[8][4];
    #pragma unroll
    for (int r = 0; r < 8; r++)
        #pragma unroll
        for (int j = 0; j < 4; j++) acc[r][j] = 0ull;

    int ar = tid >> 2, akq = tid & 3;      // A loader: rows ar, ar+64; float4 slot akq
    int bc = tid & 63, bk = tid >> 6;      // B loader: col bc, 4 k's

    for (int k0 = 0; k0 < 1024; k0 += 16) {
        float4 v0 = *(const float4*)&A[(row0 + ar     )*1024 + k0 + akq*4];
        float4 v1 = *(const float4*)&A[(row0 + ar + 64)*1024 + k0 + akq*4];
        *(float4*)&As[ ar      *20 + akq*4] = v0;
        *(float4*)&As[(ar + 64)*20 + akq*4] = v1;
        #pragma unroll
        for (int m = 0; m < 4; m++) {
            int kk = bk*4 + m;
            Bs[bc*18 + kk] = Bm[(k0 + kk)*ldb + dcol0 + bc];
        }
        __syncthreads();
        #pragma unroll
        for (int kp = 0; kp < 8; kp++) {
            ull a[8], bb[4];
            #pragma unroll
            for (int r = 0; r < 8; r++) a[r] = *(const ull*)&As[(ty*8 + r)*20 + 2*kp];
            #pragma unroll
            for (int j = 0; j < 4; j++) bb[j] = *(const ull*)&Bs[(tx + 16*j)*18 + 2*kp];
            #pragma unroll
            for (int r = 0; r < 8; r++)
                #pragma unroll
                for (int j = 0; j < 4; j++) ffma2(acc[r][j], a[r], bb[j]);
        }
        __syncthreads();
    }

    #pragma unroll
    for (int r = 0; r < 8; r++) {
        int row = row0 + ty*8 + r;
        float g0 = 0.f, g1 = 0.f, g2 = 0.f, g3 = 0.f;
        if (sel == 1) {
            const float* bx4 = boxes + (b*NN + row)*4;
            float x0 = bx4[0]*(1.0f/800.0f), y0 = bx4[1]*(1.0f/800.0f);
            float x1 = bx4[2]*(1.0f/800.0f), y1 = bx4[3]*(1.0f/800.0f);
            g0 = x0; g1 = y0; g2 = x1 - x0; g3 = y1 - y0;
        }
        #pragma unroll
        for (int j = 0; j < 4; j++) {
            int c = tx + 16*j;
            ull av = acc[r][j];
            float lo = __uint_as_float((unsigned)(av & 0xffffffffull));
            float hi = __uint_as_float((unsigned)(av >> 32));
            float s = lo + hi;
            if (sel == 1) {
                s = fmaf(g0, Wg4[0*64 + c], s);
                s = fmaf(g1, Wg4[1*64 + c], s);
                s = fmaf(g2, Wg4[2*64 + c], s);
                s = fmaf(g3, Wg4[3*64 + c], s);
            }
            Cm[row*Nc + dcol0 + c] = s;
        }
    }
}

// ---------------- fused relation scores + top-8 neighbors --------------------
// 4 target rows per block: p2 rows loaded once, reused across the 4 i's.
__global__ __launch_bounds__(256) void k_rel_topk(
    const float* __restrict__ boxes,
    const float* __restrict__ fc1_w,
    const float* __restrict__ fc1_b,
    const float* __restrict__ fc2_w)
{
    int bid = blockIdx.x;
    int b = bid / 96, igrp = bid % 96;
    int i0 = igrp * 4;
    __shared__ float sp1[4][256];
    __shared__ float srow[4][NN];
    __shared__ float sbx[16];
    int tid = threadIdx.x, warp = tid >> 5, lane = tid & 31;

    #pragma unroll
    for (int q = 0; q < 4; q++)
        sp1[q][tid] = g_p1[(b*NN + i0 + q)*256 + tid] + fc1_b[tid];
    if (tid < 16) sbx[tid] = boxes[(b*NN + i0 + (tid >> 2))*4 + (tid & 3)];
    __syncthreads();

    // per-lane hoisted weights (k = lane + 32*kk)
    float w2r[8], wg0[8], wg1[8], wg2[8], wg3[8];
    #pragma unroll
    for (int kk = 0; kk < 8; kk++) {
        int k = lane + kk*32;
        w2r[kk] = fc2_w[k];
        wg0[kk] = fc1_w[2048*256 + k];
        wg1[kk] = fc1_w[2049*256 + k];
        wg2[kk] = fc1_w[2050*256 + k];
        wg3[kk] = fc1_w[2051*256 + k];
    }

    const float* p2b = g_p2 + b*NN*256;
    const float* bxb = boxes + b*NN*4;

    for (int j = warp; j < NN; j += 8) {
        float4 bj = *(const float4*)&bxb[j*4];
        float p2v[8];
        #pragma unroll
        for (int kk = 0; kk < 8; kk++) p2v[kk] = p2b[j*256 + lane + kk*32];
        #pragma unroll
        for (int q = 0; q < 4; q++) {
            float a0 = fabsf(sbx[q*4+0] - bj.x);
            float a1 = fabsf(sbx[q*4+1] - bj.y);
            float a2 = fabsf(sbx[q*4+2] - bj.z);
            float a3 = fabsf(sbx[q*4+3] - bj.w);
            float sum = 0.f;
            #pragma unroll
            for (int kk = 0; kk < 8; kk++) {
                float t = sp1[q][lane + kk*32] + p2v[kk];
                t = fmaf(a0, wg0[kk], t);
                t = fmaf(a1, wg1[kk], t);
                t = fmaf(a2, wg2[kk], t);
                t = fmaf(a3, wg3[kk], t);
                t = fmaxf(t, 0.f);
                sum = fmaf(t, w2r[kk], sum);
            }
            #pragma unroll
            for (int o = 16; o; o >>= 1) sum += __shfl_down_sync(0xffffffffu, sum, o);
            if (lane == 0)
                srow[q][j] = sum - ((j == i0 + q) ? 1e6f : 0.f);
        }
    }
    __syncthreads();

    // warp q selects top-8 for target i0+q (value desc, index asc on ties)
    if (warp < 4) {
        int q = warp, i = i0 + q;
        for (int sel = 0; sel < TOPKK; sel++) {
            float bv = -3.4e38f; int bi = 1 << 30;
            for (int j = lane; j < NN; j += 32) {
                float v = srow[q][j];
                if (v > bv || (v == bv && j < bi)) { bv = v; bi = j; }
            }
            #pragma unroll
            for (int o = 16; o; o >>= 1) {
                float ov = __shfl_xor_sync(0xffffffffu, bv, o);
                int   oi = __shfl_xor_sync(0xffffffffu, bi, o);
                if (ov > bv || (ov == bv && oi < bi)) { bv = ov; bi = oi; }
            }
            if (lane == 0) {
                g_nbr[(b*NN + i)*TOPKK + sel] = bi;
                srow[q][bi] = -3.4e38f;
            }
            __syncwarp();
        }
    }
}

// ---------------- GAT1 per-node attention coefficients -----------------------
__global__ __launch_bounds__(128) void k_asad(
    const float* __restrict__ att_src, const float* __restrict__ att_dst)
{
    int bn = blockIdx.x;
    int warp = threadIdx.x >> 5, lane = threadIdx.x & 31;   // warp == head
    const float* xw = g_xw1 + bn*1024 + warp*256;
    float s1 = 0.f, s2 = 0.f;
    #pragma unroll
    for (int it = 0; it < 8; it++) {
        int c = lane + it*32;
        float v = xw[c];
        s1 = fmaf(v, att_src[warp*256 + c], s1);
        s2 = fmaf(v, att_dst[warp*256 + c], s2);
    }
    #pragma unroll
    for (int o = 16; o; o >>= 1) {
        s1 += __shfl_down_sync(0xffffffffu, s1, o);
        s2 += __shfl_down_sync(0xffffffffu, s2, o);
    }
    if (lane == 0) { g_as1[bn*4 + warp] = s1; g_ad1[bn*4 + warp] = s2; }
}

// ---------------- deterministic incoming-edge lists (parallel scan) ----------
__global__ __launch_bounds__(128) void k_build() {
    int bn = blockIdx.x;
    int b = bn / NN, tt = bn % NN;
    const int* nb = g_nbr + b*NN*TOPKK;
    __shared__ int scnt[128];
    int tid = threadIdx.x;
    int myc[3]; int tot = 0;
    #pragma unroll
    for (int q = 0; q < 3; q++) {
        int i = tid*3 + q;
        int m = 0;
        #pragma unroll
        for (int k = 0; k < TOPKK; k++) m += (nb[i*TOPKK + k] == tt);
        myc[q] = m; tot += m;
    }
    scnt[tid] = tot;
    __syncthreads();
    for (int s = 1; s < 128; s <<= 1) {
        int v = (tid >= s) ? scnt[tid - s] : 0;
        __syncthreads();
        scnt[tid] += v;
        __syncthreads();
    }
    int off = scnt[tid] - tot;   // exclusive prefix
    int* dst = g_srcl + bn*MAXDEG;
    #pragma unroll
    for (int q = 0; q < 3; q++) {
        if (myc[q]) {
            int i = tid*3 + q;
            #pragma unroll
            for (int k = 0; k < TOPKK; k++)
                if (nb[i*TOPKK + k] == tt) dst[off++] = i;
        }
    }
    if (tid == 127) {
        int total = scnt[127];
        dst[total] = tt;             // self loop
        g_deg[bn] = total + 1;
    }
}

// ---------------- GAT layer 1: softmax + aggregate + bias + relu -------------
__global__ __launch_bounds__(256) void k_gat1(const float* __restrict__ gat1_b) {
    int bn = blockIdx.x; int b = bn / NN;
    __shared__ int   ssrc[MAXDEG];
    __shared__ float sal[NHEADS][MAXDEG];
    int tid = threadIdx.x;
    int deg = g_deg[bn];
    for (int s = tid; s < deg; s += 256) ssrc[s] = g_srcl[bn*MAXDEG + s];
    __syncthreads();

    int warp = tid >> 5, lane = tid & 31;
    if (warp < NHEADS) {
        int h = warp;
        float adv = g_ad1[bn*4 + h];
        float m = -3.4e38f;
        for (int s = lane; s < deg; s += 32) {
            float e = g_as1[(b*NN + ssrc[s])*4 + h] + adv;
            e = (e >= 0.f) ? e : 0.2f*e;
            sal[h][s] = e;
            m = fmaxf(m, e);
        }
        #pragma unroll
        for (int o = 16; o; o >>= 1) m = fmaxf(m, __shfl_xor_sync(0xffffffffu, m, o));
        float sum = 0.f;
        for (int s = lane; s < deg; s += 32) {
            float ex = expf(sal[h][s] - m);
            sal[h][s] = ex;
            sum += ex;
        }
        #pragma unroll
        for (int o = 16; o; o >>= 1) sum += __shfl_xor_sync(0xffffffffu, sum, o);
        float inv = 1.f / fmaxf(sum, 1e-16f);
        for (int s = lane; s < deg; s += 32) sal[h][s] *= inv;
    }
    __syncthreads();

    const float* xwb = g_xw1 + b*NN*1024;
    #pragma unroll
    for (int h = 0; h < NHEADS; h++) {
        float acc0 = 0.f, acc1 = 0.f, acc2 = 0.f, acc3 = 0.f;
        int s = 0;
        for (; s + 3 < deg; s += 4) {
            acc0 = fmaf(xwb[ssrc[s+0]*1024 + h*256 + tid], sal[h][s+0], acc0);
            acc1 = fmaf(xwb[ssrc[s+1]*1024 + h*256 + tid], sal[h][s+1], acc1);
            acc2 = fmaf(xwb[ssrc[s+2]*1024 + h*256 + tid], sal[h][s+2], acc2);
            acc3 = fmaf(xwb[ssrc[s+3]*1024 + h*256 + tid], sal[h][s+3], acc3);
        }
        for (; s < deg; s++)
            acc0 = fmaf(xwb[ssrc[s]*1024 + h*256 + tid], sal[h][s], acc0);
        float o = (acc0 + acc1) + (acc2 + acc3) + gat1_b[h*256 + tid];
        g_h1[bn*1024 + h*256 + tid] = fmaxf(o, 0.f);
    }
}

// ---------------- GAT2 projection + coefficients ------------------------------
__global__ __launch_bounds__(64) void k_xw2(
    const float* __restrict__ gat2_w,
    const float* __restrict__ att_src2,
    const float* __restrict__ att_dst2)
{
    int bn = blockIdx.x;
    __shared__ float sx[2];
    int warp = threadIdx.x >> 5, lane = threadIdx.x & 31;  // warp == output channel
    const float* h1 = g_h1 + bn*1024;
    float s = 0.f;
    #pragma unroll
    for (int it = 0; it < 32; it++) {
        int k = lane + it*32;
        s = fmaf(h1[k], gat2_w[k*2 + warp], s);
    }
    #pragma unroll
    for (int o = 16; o; o >>= 1) s += __shfl_down_sync(0xffffffffu, s, o);
    if (lane == 0) { g_xw2[bn*2 + warp] = s; sx[warp] = s; }
    __syncthreads();
    if (threadIdx.x == 0) {
        g_as2[bn] = sx[0]*att_src2[0] + sx[1]*att_src2[1];
        g_ad2[bn] = sx[0]*att_dst2[0] + sx[1]*att_dst2[1];
    }
}

// ---------------- GAT layer 2: softmax + aggregate -> logits -----------------
__global__ __launch_bounds__(32) void k_gat2(const float* __restrict__ gat2_b,
                                             float* __restrict__ out)
{
    int bn = blockIdx.x; int b = bn / NN;
    __shared__ float sal[MAXDEG];
    __shared__ int   ssrc[MAXDEG];
    int lane = threadIdx.x;
    int deg = g_deg[bn];
    for (int s = lane; s < deg; s += 32) ssrc[s] = g_srcl[bn*MAXDEG + s];
    __syncwarp();
    float adv = g_ad2[bn];
    float m = -3.4e38f;
    for (int s = lane; s < deg; s += 32) {
        float e = g_as2[b*NN + ssrc[s]] + adv;
        e = (e >= 0.f) ? e : 0.2f*e;
        sal[s] = e;
        m = fmaxf(m, e);
    }
    #pragma unroll
    for (int o = 16; o; o >>= 1) m = fmaxf(m, __shfl_xor_sync(0xffffffffu, m, o));
    float sum = 0.f;
    for (int s = lane; s < deg; s += 32) {
        float ex = expf(sal[s] - m);
        sal[s] = ex;
        sum += ex;
    }
    #pragma unroll
    for (int o = 16; o; o >>= 1) sum += __shfl_xor_sync(0xffffffffu, sum, o);
    float inv = 1.f / fmaxf(sum, 1e-16f);
    __syncwarp();
    if (lane < 2) {
        float acc = 0.f;
        for (int s = 0; s < deg; s++)
            acc = fmaf(g_xw2[(b*NN + ssrc[s])*2 + lane], sal[s]*inv, acc);
        out[bn*2 + lane] = acc + gat2_b[lane];
    }
}

// ---------------- launch ------------------------------------------------------
extern "C" void kernel_launch(void* const* d_in, const int* in_sizes, int n_in,
                              void* d_out, int out_size)
{
    const float* feats   = (const float*)d_in[0];
    const float* boxes   = (const float*)d_in[1];
    const float* fc1_w   = (const float*)d_in[2];
    const float* fc1_b   = (const float*)d_in[3];
    const float* fc2_w   = (const float*)d_in[4];
    // d_in[5] = fc2_b : constant shift, irrelevant for top-k
    const float* gat1_w  = (const float*)d_in[6];
    const float* g1as    = (const float*)d_in[7];
    const float* g1ad    = (const float*)d_in[8];
    const float* gat1_b  = (const float*)d_in[9];
    const float* gat2_w  = (const float*)d_in[10];
    const float* g2as    = (const float*)d_in[11];
    const float* g2ad    = (const float*)d_in[12];
    const float* gat2_b  = (const float*)d_in[13];
    float* out = (float*)d_out;

    k_gemms   <<<144, 256>>>(feats, fc1_w, gat1_w, boxes);
    k_rel_topk<<<BB*96, 256>>>(boxes, fc1_w, fc1_b, fc2_w);
    k_asad    <<<BB*NN, 128>>>(g1as, g1ad);
    k_build   <<<BB*NN, 128>>>();
    k_gat1    <<<BB*NN, 256>>>(gat1_b);
    k_xw2     <<<BB*NN, 64>>>(gat2_w, g2as, g2ad);
    k_gat2    <<<BB*NN, 32>>>(gat2_b, out);
    (void)in_sizes; (void)n_in; (void)out_size;
}

// round 4
// speedup vs baseline: 2.0134x; 1.0712x over previous
#include <cuda_runtime.h>
#include <math.h>

#define BB 2
#define NN 384
#define CC 1024
#define HREPN 256
#define GHID 256
#define NHEADS 4
#define TOPKK 8
#define MAXDEG 400

typedef unsigned long long ull;

// ---------------- scratch (device globals; no allocation allowed) ------------
__device__ __align__(16) float g_p1 [BB*NN*HREPN];
__device__ __align__(16) float g_p2 [BB*NN*HREPN];
__device__ __align__(16) float g_xw1[BB*NN*NHEADS*GHID];
__device__ float g_as1[BB*NN*NHEADS];
__device__ float g_ad1[BB*NN*NHEADS];
__device__ int   g_nbr[BB*NN*TOPKK];
__device__ int   g_srcl[BB*NN*MAXDEG];
__device__ int   g_deg [BB*NN];
__device__ float g_xw2[BB*NN*2];
__device__ float g_as2[BB*NN];
__device__ float g_ad2[BB*NN];

// ---------------- f32x2 helpers (only add/mul/fma exist in PTX!) -------------
__device__ __forceinline__ void ffma2(ull &d, ull a, ull b) {
    asm("fma.rn.f32x2 %0, %1, %2, %0;" : "+l"(d) : "l"(a), "l"(b));
}
__device__ __forceinline__ ull fma2v(ull a, ull b, ull c) {
    ull r; asm("fma.rn.f32x2 %0, %1, %2, %3;" : "=l"(r) : "l"(a), "l"(b), "l"(c)); return r;
}
__device__ __forceinline__ ull add2v(ull a, ull b) {
    ull r; asm("add.rn.f32x2 %0, %1, %2;" : "=l"(r) : "l"(a), "l"(b)); return r;
}
__device__ __forceinline__ ull pack2(float lo, float hi) {
    ull r; asm("mov.b64 %0, {%1, %2};" : "=l"(r) : "f"(lo), "f"(hi)); return r;
}
__device__ __forceinline__ void unpack2(ull v, float &lo, float &hi) {
    asm("mov.b64 {%0, %1}, %2;" : "=f"(lo), "=f"(hi) : "l"(v));
}
__device__ __forceinline__ float lo2(ull v) { return __uint_as_float((unsigned)(v & 0xffffffffull)); }
__device__ __forceinline__ float hi2(ull v) { return __uint_as_float((unsigned)(v >> 32)); }

// ---------------- fused SGEMM dispatcher (double-buffered pipeline) ----------
// 128x64 tiles, 256 threads, 8x4 per-thread blocking, f32x2 FMA, 2-stage smem.
__global__ __launch_bounds__(256) void k_gemms(
    const float* __restrict__ feats,
    const float* __restrict__ fc1_w,
    const float* __restrict__ gat1_w,
    const float* __restrict__ boxes)
{
    __shared__ float As[2][128*20];   // [row][k], ld=20
    __shared__ float Bs[2][64*20];    // [col][k], ld=20 (16B-aligned float4 rows)
    __shared__ float Wg4[4*64];

    int tid = threadIdx.x;
    int bid = blockIdx.x;
    int sel, b, by, bx;
    if (bid < 48) { sel = 0; b = bid / 24; int r = bid % 24; by = r / 8;  bx = r % 8;  }
    else { sel = 1; int r = bid - 48; b = r / 48; r %= 48;   by = r / 16; bx = r % 16; }

    int row0 = by * 128, col0 = bx * 64;

    const float* A = feats + b*NN*CC;
    const float* Bm; float* Cm;
    int ldb, Nc, dcol0;
    if (sel == 0) {
        ldb = 256; Nc = 256;
        if (col0 < 256) { Bm = fc1_w;            Cm = g_p1 + b*NN*256; dcol0 = col0; }
        else            { Bm = fc1_w + 1024*256; Cm = g_p2 + b*NN*256; dcol0 = col0 - 256; }
    } else {
        ldb = 1024; Nc = 1024; Bm = gat1_w; Cm = g_xw1 + b*NN*1024; dcol0 = col0;
        int d = tid >> 6, c = tid & 63;
        Wg4[d*64 + c] = gat1_w[(1024 + d)*1024 + col0 + c];
    }

    int tx = tid & 15, ty = tid >> 4;
    ull acc[8][4];
    #pragma unroll
    for (int r = 0; r < 8; r++)
        #pragma unroll
        for (int j = 0; j < 4; j++) acc[r][j] = 0ull;

    int ar = tid >> 2, akq = tid & 3;      // A loader: rows ar, ar+64; float4 slot akq
    int bc = tid & 63, bk = tid >> 6;      // B loader: col bc, k's bk*4..+3

    const float* Ap0 = A + (row0 + ar)*1024 + akq*4;
    const float* Ap1 = Ap0 + 64*1024;
    const float* Bp  = Bm + dcol0 + bc;

    // prologue: fetch tile 0
    float4 pv0 = *(const float4*)Ap0;
    float4 pv1 = *(const float4*)Ap1;
    float pb0 = Bp[(bk*4+0)*ldb];
    float pb1 = Bp[(bk*4+1)*ldb];
    float pb2 = Bp[(bk*4+2)*ldb];
    float pb3 = Bp[(bk*4+3)*ldb];
    *(float4*)&As[0][ ar      *20 + akq*4] = pv0;
    *(float4*)&As[0][(ar + 64)*20 + akq*4] = pv1;
    Bs[0][bc*20 + bk*4+0] = pb0;
    Bs[0][bc*20 + bk*4+1] = pb1;
    Bs[0][bc*20 + bk*4+2] = pb2;
    Bs[0][bc*20 + bk*4+3] = pb3;
    __syncthreads();

    for (int t = 0; t < 64; t++) {
        int cur = t & 1, nxt = cur ^ 1;
        if (t < 63) {
            int k0 = (t + 1) * 16;
            pv0 = *(const float4*)(Ap0 + k0);
            pv1 = *(const float4*)(Ap1 + k0);
            pb0 = Bp[(k0 + bk*4+0)*ldb];
            pb1 = Bp[(k0 + bk*4+1)*ldb];
            pb2 = Bp[(k0 + bk*4+2)*ldb];
            pb3 = Bp[(k0 + bk*4+3)*ldb];
        }
        #pragma unroll
        for (int kph = 0; kph < 4; kph++) {
            ulonglong2 a2[8], b2[4];
            #pragma unroll
            for (int r = 0; r < 8; r++)
                a2[r] = *(const ulonglong2*)&As[cur][(ty*8 + r)*20 + kph*4];
            #pragma unroll
            for (int j = 0; j < 4; j++)
                b2[j] = *(const ulonglong2*)&Bs[cur][(tx + 16*j)*20 + kph*4];
            #pragma unroll
            for (int r = 0; r < 8; r++)
                #pragma unroll
                for (int j = 0; j < 4; j++) ffma2(acc[r][j], a2[r].x, b2[j].x);
            #pragma unroll
            for (int r = 0; r < 8; r++)
                #pragma unroll
                for (int j = 0; j < 4; j++) ffma2(acc[r][j], a2[r].y, b2[j].y);
        }
        if (t < 63) {
            *(float4*)&As[nxt][ ar      *20 + akq*4] = pv0;
            *(float4*)&As[nxt][(ar + 64)*20 + akq*4] = pv1;
            Bs[nxt][bc*20 + bk*4+0] = pb0;
            Bs[nxt][bc*20 + bk*4+1] = pb1;
            Bs[nxt][bc*20 + bk*4+2] = pb2;
            Bs[nxt][bc*20 + bk*4+3] = pb3;
        }
        __syncthreads();
    }

    #pragma unroll
    for (int r = 0; r < 8; r++) {
        int row = row0 + ty*8 + r;
        float g0 = 0.f, g1 = 0.f, g2 = 0.f, g3 = 0.f;
        if (sel == 1) {
            const float* bx4 = boxes + (b*NN + row)*4;
            float x0 = bx4[0]*(1.0f/800.0f), y0 = bx4[1]*(1.0f/800.0f);
            float x1 = bx4[2]*(1.0f/800.0f), y1 = bx4[3]*(1.0f/800.0f);
            g0 = x0; g1 = y0; g2 = x1 - x0; g3 = y1 - y0;
        }
        #pragma unroll
        for (int j = 0; j < 4; j++) {
            int c = tx + 16*j;
            float s = lo2(acc[r][j]) + hi2(acc[r][j]);
            if (sel == 1) {
                s = fmaf(g0, Wg4[0*64 + c], s);
                s = fmaf(g1, Wg4[1*64 + c], s);
                s = fmaf(g2, Wg4[2*64 + c], s);
                s = fmaf(g3, Wg4[3*64 + c], s);
            }
            Cm[row*Nc + dcol0 + c] = s;
        }
    }
}

// ---------------- fused relation scores + top-8 (f32x2 inner) ----------------
__global__ __launch_bounds__(256) void k_rel_topk(
    const float* __restrict__ boxes,
    const float* __restrict__ fc1_w,
    const float* __restrict__ fc1_b,
    const float* __restrict__ fc2_w)
{
    int bid = blockIdx.x;
    int b = bid / 96, igrp = bid % 96;
    int i0 = igrp * 4;
    __shared__ float srow[4][NN];
    __shared__ float sbx[16];
    int tid = threadIdx.x, warp = tid >> 5, lane = tid & 31;

    if (tid < 16) sbx[tid] = boxes[(b*NN + i0 + (tid >> 2))*4 + (tid & 3)];

    // per-lane hoisted packed weights/bias/p1: pair (k, k+32), k = lane + 64p
    ull wg2[4][4], sp1q[4][4];
    float w2lo[4], w2hi[4];
    #pragma unroll
    for (int p = 0; p < 4; p++) {
        int k0 = lane + 64*p, k1 = k0 + 32;
        w2lo[p] = fc2_w[k0];
        w2hi[p] = fc2_w[k1];
        #pragma unroll
        for (int d = 0; d < 4; d++)
            wg2[d][p] = pack2(fc1_w[(2048+d)*256 + k0], fc1_w[(2048+d)*256 + k1]);
        float b0 = fc1_b[k0], b1 = fc1_b[k1];
        #pragma unroll
        for (int q = 0; q < 4; q++) {
            const float* p1r = g_p1 + (b*NN + i0 + q)*256;
            sp1q[q][p] = pack2(p1r[k0] + b0, p1r[k1] + b1);
        }
    }
    __syncthreads();

    const float* p2b = g_p2 + b*NN*256;
    const float* bxb = boxes + b*NN*4;

    for (int j = warp; j < NN; j += 8) {
        float4 bj = *(const float4*)&bxb[j*4];
        ull p2v[4];
        #pragma unroll
        for (int p = 0; p < 4; p++) {
            int k0 = lane + 64*p;
            p2v[p] = pack2(p2b[j*256 + k0], p2b[j*256 + k0 + 32]);
        }
        #pragma unroll
        for (int q = 0; q < 4; q++) {
            float d0 = fabsf(sbx[q*4+0] - bj.x);
            float d1 = fabsf(sbx[q*4+1] - bj.y);
            float d2 = fabsf(sbx[q*4+2] - bj.z);
            float d3 = fabsf(sbx[q*4+3] - bj.w);
            ull a0 = pack2(d0, d0), a1 = pack2(d1, d1);
            ull a2 = pack2(d2, d2), a3 = pack2(d3, d3);
            float sum = 0.f;
            #pragma unroll
            for (int p = 0; p < 4; p++) {
                ull t = add2v(sp1q[q][p], p2v[p]);
                t = fma2v(a0, wg2[0][p], t);
                t = fma2v(a1, wg2[1][p], t);
                t = fma2v(a2, wg2[2][p], t);
                t = fma2v(a3, wg2[3][p], t);
                float tl, th;
                unpack2(t, tl, th);
                tl = fmaxf(tl, 0.f);
                th = fmaxf(th, 0.f);
                sum = fmaf(tl, w2lo[p], sum);
                sum = fmaf(th, w2hi[p], sum);
            }
            #pragma unroll
            for (int o = 16; o; o >>= 1) sum += __shfl_down_sync(0xffffffffu, sum, o);
            if (lane == 0)
                srow[q][j] = sum - ((j == i0 + q) ? 1e6f : 0.f);
        }
    }
    __syncthreads();

    // warp q selects top-8 for target i0+q (value desc, index asc on ties)
    if (warp < 4) {
        int q = warp, i = i0 + q;
        for (int sel = 0; sel < TOPKK; sel++) {
            float bv = -3.4e38f; int bi = 1 << 30;
            for (int j = lane; j < NN; j += 32) {
                float v = srow[q][j];
                if (v > bv || (v == bv && j < bi)) { bv = v; bi = j; }
            }
            #pragma unroll
            for (int o = 16; o; o >>= 1) {
                float ov = __shfl_xor_sync(0xffffffffu, bv, o);
                int   oi = __shfl_xor_sync(0xffffffffu, bi, o);
                if (ov > bv || (ov == bv && oi < bi)) { bv = ov; bi = oi; }
            }
            if (lane == 0) {
                g_nbr[(b*NN + i)*TOPKK + sel] = bi;
                srow[q][bi] = -3.4e38f;
            }
            __syncwarp();
        }
    }
}

// ---------------- merged: GAT1 coefficients (asad) + edge-list build ---------
__global__ __launch_bounds__(128) void k_mid(
    const float* __restrict__ att_src, const float* __restrict__ att_dst)
{
    int bid = blockIdx.x;
    if (bid < BB*NN) {
        // ---- asad role ----
        int bn = bid;
        int warp = threadIdx.x >> 5, lane = threadIdx.x & 31;   // warp == head
        const float* xw = g_xw1 + bn*1024 + warp*256;
        float s1 = 0.f, s2 = 0.f;
        #pragma unroll
        for (int it = 0; it < 8; it++) {
            int c = lane + it*32;
            float v = xw[c];
            s1 = fmaf(v, att_src[warp*256 + c], s1);
            s2 = fmaf(v, att_dst[warp*256 + c], s2);
        }
        #pragma unroll
        for (int o = 16; o; o >>= 1) {
            s1 += __shfl_down_sync(0xffffffffu, s1, o);
            s2 += __shfl_down_sync(0xffffffffu, s2, o);
        }
        if (lane == 0) { g_as1[bn*4 + warp] = s1; g_ad1[bn*4 + warp] = s2; }
    } else {
        // ---- build role: deterministic incoming-edge lists ----
        int bn = bid - BB*NN;
        int b = bn / NN, tt = bn % NN;
        const int* nb = g_nbr + b*NN*TOPKK;
        __shared__ int scnt[128];
        int tid = threadIdx.x;
        int myc[3]; int tot = 0;
        #pragma unroll
        for (int q = 0; q < 3; q++) {
            int i = tid*3 + q;
            int m = 0;
            #pragma unroll
            for (int k = 0; k < TOPKK; k++) m += (nb[i*TOPKK + k] == tt);
            myc[q] = m; tot += m;
        }
        scnt[tid] = tot;
        __syncthreads();
        for (int s = 1; s < 128; s <<= 1) {
            int v = (tid >= s) ? scnt[tid - s] : 0;
            __syncthreads();
            scnt[tid] += v;
            __syncthreads();
        }
        int off = scnt[tid] - tot;   // exclusive prefix
        int* dst = g_srcl + bn*MAXDEG;
        #pragma unroll
        for (int q = 0; q < 3; q++) {
            if (myc[q]) {
                int i = tid*3 + q;
                #pragma unroll
                for (int k = 0; k < TOPKK; k++)
                    if (nb[i*TOPKK + k] == tt) dst[off++] = i;
            }
        }
        if (tid == 127) {
            int total = scnt[127];
            dst[total] = tt;             // self loop
            g_deg[bn] = total + 1;
        }
    }
}

// ---------------- GAT layer 1 + fused GAT2 projection/coefficients -----------
__global__ __launch_bounds__(256) void k_gat1(
    const float* __restrict__ gat1_b,
    const float* __restrict__ gat2_w,
    const float* __restrict__ att_src2,
    const float* __restrict__ att_dst2)
{
    int bn = blockIdx.x; int b = bn / NN;
    __shared__ int   ssrc[MAXDEG];
    __shared__ float sal[NHEADS][MAXDEG];
    __shared__ float red[8][2];
    int tid = threadIdx.x;
    int deg = g_deg[bn];
    for (int s = tid; s < deg; s += 256) ssrc[s] = g_srcl[bn*MAXDEG + s];
    __syncthreads();

    int warp = tid >> 5, lane = tid & 31;
    if (warp < NHEADS) {
        int h = warp;
        float adv = g_ad1[bn*4 + h];
        float m = -3.4e38f;
        for (int s = lane; s < deg; s += 32) {
            float e = g_as1[(b*NN + ssrc[s])*4 + h] + adv;
            e = (e >= 0.f) ? e : 0.2f*e;
            sal[h][s] = e;
            m = fmaxf(m, e);
        }
        #pragma unroll
        for (int o = 16; o; o >>= 1) m = fmaxf(m, __shfl_xor_sync(0xffffffffu, m, o));
        float sum = 0.f;
        for (int s = lane; s < deg; s += 32) {
            float ex = expf(sal[h][s] - m);
            sal[h][s] = ex;
            sum += ex;
        }
        #pragma unroll
        for (int o = 16; o; o >>= 1) sum += __shfl_xor_sync(0xffffffffu, sum, o);
        float inv = 1.f / fmaxf(sum, 1e-16f);
        for (int s = lane; s < deg; s += 32) sal[h][s] *= inv;
    }
    __syncthreads();

    const float* xwb = g_xw1 + b*NN*1024;
    float oh[NHEADS];
    #pragma unroll
    for (int h = 0; h < NHEADS; h++) {
        float acc0 = 0.f, acc1 = 0.f, acc2 = 0.f, acc3 = 0.f;
        int s = 0;
        for (; s + 3 < deg; s += 4) {
            acc0 = fmaf(xwb[ssrc[s+0]*1024 + h*256 + tid], sal[h][s+0], acc0);
            acc1 = fmaf(xwb[ssrc[s+1]*1024 + h*256 + tid], sal[h][s+1], acc1);
            acc2 = fmaf(xwb[ssrc[s+2]*1024 + h*256 + tid], sal[h][s+2], acc2);
            acc3 = fmaf(xwb[ssrc[s+3]*1024 + h*256 + tid], sal[h][s+3], acc3);
        }
        for (; s < deg; s++)
            acc0 = fmaf(xwb[ssrc[s]*1024 + h*256 + tid], sal[h][s], acc0);
        float o = (acc0 + acc1) + (acc2 + acc3) + gat1_b[h*256 + tid];
        oh[h] = fmaxf(o, 0.f);
    }

    // fused xw2 = h1 @ gat2_w  (block reduction over 1024 cols)
    float c0 = 0.f, c1 = 0.f;
    #pragma unroll
    for (int h = 0; h < NHEADS; h++) {
        int col = h*256 + tid;
        c0 = fmaf(oh[h], gat2_w[col*2 + 0], c0);
        c1 = fmaf(oh[h], gat2_w[col*2 + 1], c1);
    }
    #pragma unroll
    for (int o = 16; o; o >>= 1) {
        c0 += __shfl_down_sync(0xffffffffu, c0, o);
        c1 += __shfl_down_sync(0xffffffffu, c1, o);
    }
    if (lane == 0) { red[warp][0] = c0; red[warp][1] = c1; }
    __syncthreads();
    if (tid == 0) {
        float s0 = 0.f, s1 = 0.f;
        #pragma unroll
        for (int w = 0; w < 8; w++) { s0 += red[w][0]; s1 += red[w][1]; }
        g_xw2[bn*2 + 0] = s0;
        g_xw2[bn*2 + 1] = s1;
        g_as2[bn] = s0*att_src2[0] + s1*att_src2[1];
        g_ad2[bn] = s0*att_dst2[0] + s1*att_dst2[1];
    }
}

// ---------------- GAT layer 2: softmax + aggregate -> logits -----------------
__global__ __launch_bounds__(32) void k_gat2(const float* __restrict__ gat2_b,
                                             float* __restrict__ out)
{
    int bn = blockIdx.x; int b = bn / NN;
    __shared__ float sal[MAXDEG];
    __shared__ int   ssrc[MAXDEG];
    int lane = threadIdx.x;
    int deg = g_deg[bn];
    for (int s = lane; s < deg; s += 32) ssrc[s] = g_srcl[bn*MAXDEG + s];
    __syncwarp();
    float adv = g_ad2[bn];
    float m = -3.4e38f;
    for (int s = lane; s < deg; s += 32) {
        float e = g_as2[b*NN + ssrc[s]] + adv;
        e = (e >= 0.f) ? e : 0.2f*e;
        sal[s] = e;
        m = fmaxf(m, e);
    }
    #pragma unroll
    for (int o = 16; o; o >>= 1) m = fmaxf(m, __shfl_xor_sync(0xffffffffu, m, o));
    float sum = 0.f;
    for (int s = lane; s < deg; s += 32) {
        float ex = expf(sal[s] - m);
        sal[s] = ex;
        sum += ex;
    }
    #pragma unroll
    for (int o = 16; o; o >>= 1) sum += __shfl_xor_sync(0xffffffffu, sum, o);
    float inv = 1.f / fmaxf(sum, 1e-16f);
    __syncwarp();
    if (lane < 2) {
        float acc = 0.f;
        for (int s = 0; s < deg; s++)
            acc = fmaf(g_xw2[(b*NN + ssrc[s])*2 + lane], sal[s]*inv, acc);
        out[bn*2 + lane] = acc + gat2_b[lane];
    }
}

// ---------------- launch ------------------------------------------------------
extern "C" void kernel_launch(void* const* d_in, const int* in_sizes, int n_in,
                              void* d_out, int out_size)
{
    const float* feats   = (const float*)d_in[0];
    const float* boxes   = (const float*)d_in[1];
    const float* fc1_w   = (const float*)d_in[2];
    const float* fc1_b   = (const float*)d_in[3];
    const float* fc2_w   = (const float*)d_in[4];
    // d_in[5] = fc2_b : constant shift, irrelevant for top-k
    const float* gat1_w  = (const float*)d_in[6];
    const float* g1as    = (const float*)d_in[7];
    const float* g1ad    = (const float*)d_in[8];
    const float* gat1_b  = (const float*)d_in[9];
    const float* gat2_w  = (const float*)d_in[10];
    const float* g2as    = (const float*)d_in[11];
    const float* g2ad    = (const float*)d_in[12];
    const float* gat2_b  = (const float*)d_in[13];
    float* out = (float*)d_out;

    k_gemms   <<<144, 256>>>(feats, fc1_w, gat1_w, boxes);
    k_rel_topk<<<BB*96, 256>>>(boxes, fc1_w, fc1_b, fc2_w);
    k_mid     <<<2*BB*NN, 128>>>(g1as, g1ad);
    k_gat1    <<<BB*NN, 256>>>(gat1_b, gat2_w, g2as, g2ad);
    k_gat2    <<<BB*NN, 32>>>(gat2_b, out);
    (void)in_sizes; (void)n_in; (void)out_size;
}

// round 5
// speedup vs baseline: 2.1710x; 1.0783x over previous
#include <cuda_runtime.h>
#include <math.h>

#define BB 2
#define NN 384
#define CC 1024
#define HREPN 256
#define GHID 256
#define NHEADS 4
#define TOPKK 8
#define MAXDEG 400

typedef unsigned long long ull;

// ---------------- scratch (device globals; no allocation allowed) ------------
__device__ __align__(16) float g_p1 [BB*NN*HREPN];
__device__ __align__(16) float g_p2 [BB*NN*HREPN];
__device__ __align__(16) float g_xw1[BB*NN*NHEADS*GHID];
__device__ float g_as1[BB*NN*NHEADS];
__device__ float g_ad1[BB*NN*NHEADS];
__device__ int   g_nbr[BB*NN*TOPKK];
__device__ int   g_srcl[BB*NN*MAXDEG];
__device__ int   g_deg [BB*NN];
__device__ float g_xw2[BB*NN*2];
__device__ float g_as2[BB*NN];
__device__ float g_ad2[BB*NN];

// ---------------- f32x2 helpers (only add/mul/fma exist in PTX) --------------
__device__ __forceinline__ void ffma2(ull &d, ull a, ull b) {
    asm("fma.rn.f32x2 %0, %1, %2, %0;" : "+l"(d) : "l"(a), "l"(b));
}
__device__ __forceinline__ ull fma2v(ull a, ull b, ull c) {
    ull r; asm("fma.rn.f32x2 %0, %1, %2, %3;" : "=l"(r) : "l"(a), "l"(b), "l"(c)); return r;
}
__device__ __forceinline__ ull add2v(ull a, ull b) {
    ull r; asm("add.rn.f32x2 %0, %1, %2;" : "=l"(r) : "l"(a), "l"(b)); return r;
}
__device__ __forceinline__ ull pack2(float lo, float hi) {
    ull r; asm("mov.b64 %0, {%1, %2};" : "=l"(r) : "f"(lo), "f"(hi)); return r;
}
__device__ __forceinline__ void unpack2(ull v, float &lo, float &hi) {
    asm("mov.b64 {%0, %1}, %2;" : "=f"(lo), "=f"(hi) : "l"(v));
}
__device__ __forceinline__ float lo2(ull v) { return __uint_as_float((unsigned)(v & 0xffffffffull)); }
__device__ __forceinline__ float hi2(ull v) { return __uint_as_float((unsigned)(v >> 32)); }

// ---------------- fused SGEMM dispatcher (double-buffered pipeline) ----------
__global__ __launch_bounds__(256) void k_gemms(
    const float* __restrict__ feats,
    const float* __restrict__ fc1_w,
    const float* __restrict__ gat1_w,
    const float* __restrict__ boxes)
{
    __shared__ float As[2][128*20];   // [row][k], ld=20
    __shared__ float Bs[2][64*20];    // [col][k], ld=20
    __shared__ float Wg4[4*64];

    int tid = threadIdx.x;
    int bid = blockIdx.x;
    int sel, b, by, bx;
    if (bid < 48) { sel = 0; b = bid / 24; int r = bid % 24; by = r / 8;  bx = r % 8;  }
    else { sel = 1; int r = bid - 48; b = r / 48; r %= 48;   by = r / 16; bx = r % 16; }

    int row0 = by * 128, col0 = bx * 64;

    const float* A = feats + b*NN*CC;
    const float* Bm; float* Cm;
    int ldb, Nc, dcol0;
    if (sel == 0) {
        ldb = 256; Nc = 256;
        if (col0 < 256) { Bm = fc1_w;            Cm = g_p1 + b*NN*256; dcol0 = col0; }
        else            { Bm = fc1_w + 1024*256; Cm = g_p2 + b*NN*256; dcol0 = col0 - 256; }
    } else {
        ldb = 1024; Nc = 1024; Bm = gat1_w; Cm = g_xw1 + b*NN*1024; dcol0 = col0;
        int d = tid >> 6, c = tid & 63;
        Wg4[d*64 + c] = gat1_w[(1024 + d)*1024 + col0 + c];
    }

    int tx = tid & 15, ty = tid >> 4;
    ull acc[8][4];
    #pragma unroll
    for (int r = 0; r < 8; r++)
        #pragma unroll
        for (int j = 0; j < 4; j++) acc[r][j] = 0ull;

    int ar = tid >> 2, akq = tid & 3;
    int bc = tid & 63, bk = tid >> 6;

    const float* Ap0 = A + (row0 + ar)*1024 + akq*4;
    const float* Ap1 = Ap0 + 64*1024;
    const float* Bp  = Bm + dcol0 + bc;

    float4 pv0 = *(const float4*)Ap0;
    float4 pv1 = *(const float4*)Ap1;
    float pb0 = Bp[(bk*4+0)*ldb];
    float pb1 = Bp[(bk*4+1)*ldb];
    float pb2 = Bp[(bk*4+2)*ldb];
    float pb3 = Bp[(bk*4+3)*ldb];
    *(float4*)&As[0][ ar      *20 + akq*4] = pv0;
    *(float4*)&As[0][(ar + 64)*20 + akq*4] = pv1;
    Bs[0][bc*20 + bk*4+0] = pb0;
    Bs[0][bc*20 + bk*4+1] = pb1;
    Bs[0][bc*20 + bk*4+2] = pb2;
    Bs[0][bc*20 + bk*4+3] = pb3;
    __syncthreads();

    for (int t = 0; t < 64; t++) {
        int cur = t & 1, nxt = cur ^ 1;
        if (t < 63) {
            int k0 = (t + 1) * 16;
            pv0 = *(const float4*)(Ap0 + k0);
            pv1 = *(const float4*)(Ap1 + k0);
            pb0 = Bp[(k0 + bk*4+0)*ldb];
            pb1 = Bp[(k0 + bk*4+1)*ldb];
            pb2 = Bp[(k0 + bk*4+2)*ldb];
            pb3 = Bp[(k0 + bk*4+3)*ldb];
        }
        #pragma unroll
        for (int kph = 0; kph < 4; kph++) {
            ulonglong2 a2[8], b2[4];
            #pragma unroll
            for (int r = 0; r < 8; r++)
                a2[r] = *(const ulonglong2*)&As[cur][(ty*8 + r)*20 + kph*4];
            #pragma unroll
            for (int j = 0; j < 4; j++)
                b2[j] = *(const ulonglong2*)&Bs[cur][(tx + 16*j)*20 + kph*4];
            #pragma unroll
            for (int r = 0; r < 8; r++)
                #pragma unroll
                for (int j = 0; j < 4; j++) ffma2(acc[r][j], a2[r].x, b2[j].x);
            #pragma unroll
            for (int r = 0; r < 8; r++)
                #pragma unroll
                for (int j = 0; j < 4; j++) ffma2(acc[r][j], a2[r].y, b2[j].y);
        }
        if (t < 63) {
            *(float4*)&As[nxt][ ar      *20 + akq*4] = pv0;
            *(float4*)&As[nxt][(ar + 64)*20 + akq*4] = pv1;
            Bs[nxt][bc*20 + bk*4+0] = pb0;
            Bs[nxt][bc*20 + bk*4+1] = pb1;
            Bs[nxt][bc*20 + bk*4+2] = pb2;
            Bs[nxt][bc*20 + bk*4+3] = pb3;
        }
        __syncthreads();
    }

    #pragma unroll
    for (int r = 0; r < 8; r++) {
        int row = row0 + ty*8 + r;
        float g0 = 0.f, g1 = 0.f, g2 = 0.f, g3 = 0.f;
        if (sel == 1) {
            const float* bx4 = boxes + (b*NN + row)*4;
            float x0 = bx4[0]*(1.0f/800.0f), y0 = bx4[1]*(1.0f/800.0f);
            float x1 = bx4[2]*(1.0f/800.0f), y1 = bx4[3]*(1.0f/800.0f);
            g0 = x0; g1 = y0; g2 = x1 - x0; g3 = y1 - y0;
        }
        #pragma unroll
        for (int j = 0; j < 4; j++) {
            int c = tx + 16*j;
            float s = lo2(acc[r][j]) + hi2(acc[r][j]);
            if (sel == 1) {
                s = fmaf(g0, Wg4[0*64 + c], s);
                s = fmaf(g1, Wg4[1*64 + c], s);
                s = fmaf(g2, Wg4[2*64 + c], s);
                s = fmaf(g3, Wg4[3*64 + c], s);
            }
            Cm[row*Nc + dcol0 + c] = s;
        }
    }
}

// ------- merged: relation scores + top-8 (blocks 0..191)  |  asad (192..959) -
__global__ __launch_bounds__(256) void k_rel_asad(
    const float* __restrict__ boxes,
    const float* __restrict__ fc1_w,
    const float* __restrict__ fc1_b,
    const float* __restrict__ fc2_w,
    const float* __restrict__ att_src,
    const float* __restrict__ att_dst)
{
    __shared__ float srow[4][NN];
    __shared__ float sbx[16];
    int bid = blockIdx.x;
    int tid = threadIdx.x, warp = tid >> 5, lane = tid & 31;

    if (bid >= 192) {
        // ---- asad role: per-node GAT1 attention coefficients (float4) ----
        if (tid < 128) {
            int bn = bid - 192;
            int h = tid >> 5;   // warp == head
            const float* xw = g_xw1 + bn*1024 + h*256 + lane*8;
            float4 v0 = *(const float4*)xw;
            float4 v1 = *(const float4*)(xw + 4);
            const float* asr = att_src + h*256 + lane*8;
            const float* adr = att_dst + h*256 + lane*8;
            float4 s0 = *(const float4*)asr;
            float4 s1 = *(const float4*)(asr + 4);
            float4 d0 = *(const float4*)adr;
            float4 d1 = *(const float4*)(adr + 4);
            float ss = v0.x*s0.x + v0.y*s0.y + v0.z*s0.z + v0.w*s0.w
                     + v1.x*s1.x + v1.y*s1.y + v1.z*s1.z + v1.w*s1.w;
            float dd = v0.x*d0.x + v0.y*d0.y + v0.z*d0.z + v0.w*d0.w
                     + v1.x*d1.x + v1.y*d1.y + v1.z*d1.z + v1.w*d1.w;
            #pragma unroll
            for (int o = 16; o; o >>= 1) {
                ss += __shfl_down_sync(0xffffffffu, ss, o);
                dd += __shfl_down_sync(0xffffffffu, dd, o);
            }
            if (lane == 0) { g_as1[bn*4 + h] = ss; g_ad1[bn*4 + h] = dd; }
        }
        return;
    }

    // ---- rel_topk role ----
    int b = bid / 96, igrp = bid % 96;
    int i0 = igrp * 4;

    if (tid < 16) sbx[tid] = boxes[(b*NN + i0 + (tid >> 2))*4 + (tid & 3)];

    ull wg2[4][4], sp1q[4][4];
    float w2lo[4], w2hi[4];
    #pragma unroll
    for (int p = 0; p < 4; p++) {
        int k0 = lane + 64*p, k1 = k0 + 32;
        w2lo[p] = fc2_w[k0];
        w2hi[p] = fc2_w[k1];
        #pragma unroll
        for (int d = 0; d < 4; d++)
            wg2[d][p] = pack2(fc1_w[(2048+d)*256 + k0], fc1_w[(2048+d)*256 + k1]);
        float b0 = fc1_b[k0], b1 = fc1_b[k1];
        #pragma unroll
        for (int q = 0; q < 4; q++) {
            const float* p1r = g_p1 + (b*NN + i0 + q)*256;
            sp1q[q][p] = pack2(p1r[k0] + b0, p1r[k1] + b1);
        }
    }
    __syncthreads();

    const float* p2b = g_p2 + b*NN*256;
    const float* bxb = boxes + b*NN*4;

    for (int j = warp; j < NN; j += 8) {
        float4 bj = *(const float4*)&bxb[j*4];
        ull p2v[4];
        #pragma unroll
        for (int p = 0; p < 4; p++) {
            int k0 = lane + 64*p;
            p2v[p] = pack2(p2b[j*256 + k0], p2b[j*256 + k0 + 32]);
        }
        #pragma unroll
        for (int q = 0; q < 4; q++) {
            float d0 = fabsf(sbx[q*4+0] - bj.x);
            float d1 = fabsf(sbx[q*4+1] - bj.y);
            float d2 = fabsf(sbx[q*4+2] - bj.z);
            float d3 = fabsf(sbx[q*4+3] - bj.w);
            ull a0 = pack2(d0, d0), a1 = pack2(d1, d1);
            ull a2 = pack2(d2, d2), a3 = pack2(d3, d3);
            float sum = 0.f;
            #pragma unroll
            for (int p = 0; p < 4; p++) {
                ull t = add2v(sp1q[q][p], p2v[p]);
                t = fma2v(a0, wg2[0][p], t);
                t = fma2v(a1, wg2[1][p], t);
                t = fma2v(a2, wg2[2][p], t);
                t = fma2v(a3, wg2[3][p], t);
                float tl, th;
                unpack2(t, tl, th);
                tl = fmaxf(tl, 0.f);
                th = fmaxf(th, 0.f);
                sum = fmaf(tl, w2lo[p], sum);
                sum = fmaf(th, w2hi[p], sum);
            }
            #pragma unroll
            for (int o = 16; o; o >>= 1) sum += __shfl_down_sync(0xffffffffu, sum, o);
            if (lane == 0)
                srow[q][j] = sum - ((j == i0 + q) ? 1e6f : 0.f);
        }
    }
    __syncthreads();

    if (warp < 4) {
        int q = warp, i = i0 + q;
        for (int sel = 0; sel < TOPKK; sel++) {
            float bv = -3.4e38f; int bi = 1 << 30;
            for (int j = lane; j < NN; j += 32) {
                float v = srow[q][j];
                if (v > bv || (v == bv && j < bi)) { bv = v; bi = j; }
            }
            #pragma unroll
            for (int o = 16; o; o >>= 1) {
                float ov = __shfl_xor_sync(0xffffffffu, bv, o);
                int   oi = __shfl_xor_sync(0xffffffffu, bi, o);
                if (ov > bv || (ov == bv && oi < bi)) { bv = ov; bi = oi; }
            }
            if (lane == 0) {
                g_nbr[(b*NN + i)*TOPKK + sel] = bi;
                srow[q][bi] = -3.4e38f;
            }
            __syncwarp();
        }
    }
}

// -------- GAT1: fused edge-build + softmax + float4 aggregate + xw2 ----------
__global__ __launch_bounds__(256) void k_gat1(
    const float* __restrict__ gat1_b,
    const float* __restrict__ gat2_w,
    const float* __restrict__ att_src2,
    const float* __restrict__ att_dst2)
{
    int bn = blockIdx.x; int b = bn / NN, tt = bn % NN;
    __shared__ int   ssrc[MAXDEG];
    __shared__ float sal[NHEADS][MAXDEG];
    __shared__ int   scnt[256];
    __shared__ float red[8][2];
    __shared__ int   sdeg;
    int tid = threadIdx.x;

    // ---- build phase: deterministic incoming-edge list for target tt ----
    const int* nb = g_nbr + b*NN*TOPKK;
    int myc0 = 0, myc1 = 0;
    int ia = 2*tid, ib = 2*tid + 1;
    if (tid < 192) {
        #pragma unroll
        for (int k = 0; k < TOPKK; k++) {
            myc0 += (nb[ia*TOPKK + k] == tt);
            myc1 += (nb[ib*TOPKK + k] == tt);
        }
    }
    int tot = myc0 + myc1;
    scnt[tid] = tot;
    __syncthreads();
    for (int s = 1; s < 256; s <<= 1) {
        int v = (tid >= s) ? scnt[tid - s] : 0;
        __syncthreads();
        scnt[tid] += v;
        __syncthreads();
    }
    int off = scnt[tid] - tot;
    int* dst = g_srcl + bn*MAXDEG;
    if (tid < 192) {
        if (myc0) {
            #pragma unroll
            for (int k = 0; k < TOPKK; k++)
                if (nb[ia*TOPKK + k] == tt) { ssrc[off] = ia; dst[off] = ia; off++; }
        }
        if (myc1) {
            #pragma unroll
            for (int k = 0; k < TOPKK; k++)
                if (nb[ib*TOPKK + k] == tt) { ssrc[off] = ib; dst[off] = ib; off++; }
        }
    }
    if (tid == 255) {
        int total = scnt[255];
        ssrc[total] = tt;
        dst[total] = tt;
        g_deg[bn] = total + 1;
        sdeg = total + 1;
    }
    __syncthreads();
    int deg = sdeg;

    // ---- softmax phase (warp h handles head h) ----
    int warp = tid >> 5, lane = tid & 31;
    if (warp < NHEADS) {
        int h = warp;
        float adv = g_ad1[bn*4 + h];
        float m = -3.4e38f;
        for (int s = lane; s < deg; s += 32) {
            float e = g_as1[(b*NN + ssrc[s])*4 + h] + adv;
            e = (e >= 0.f) ? e : 0.2f*e;
            sal[h][s] = e;
            m = fmaxf(m, e);
        }
        #pragma unroll
        for (int o = 16; o; o >>= 1) m = fmaxf(m, __shfl_xor_sync(0xffffffffu, m, o));
        float sum = 0.f;
        for (int s = lane; s < deg; s += 32) {
            float ex = expf(sal[h][s] - m);
            sal[h][s] = ex;
            sum += ex;
        }
        #pragma unroll
        for (int o = 16; o; o >>= 1) sum += __shfl_xor_sync(0xffffffffu, sum, o);
        float inv = 1.f / fmaxf(sum, 1e-16f);
        for (int s = lane; s < deg; s += 32) sal[h][s] *= inv;
    }
    __syncthreads();

    // ---- aggregate: thread owns 4 contiguous cols (float4), h = tid>>6 ----
    const float* xwb = g_xw1 + b*NN*1024;
    const float* salh = sal[tid >> 6];
    float4 acc0 = make_float4(0.f, 0.f, 0.f, 0.f);
    float4 acc1 = make_float4(0.f, 0.f, 0.f, 0.f);
    int col4 = tid * 4;
    int s = 0;
    for (; s + 1 < deg; s += 2) {
        float4 v0 = *(const float4*)&xwb[ssrc[s  ]*1024 + col4];
        float4 v1 = *(const float4*)&xwb[ssrc[s+1]*1024 + col4];
        float a0 = salh[s], a1 = salh[s+1];
        acc0.x = fmaf(v0.x, a0, acc0.x); acc0.y = fmaf(v0.y, a0, acc0.y);
        acc0.z = fmaf(v0.z, a0, acc0.z); acc0.w = fmaf(v0.w, a0, acc0.w);
        acc1.x = fmaf(v1.x, a1, acc1.x); acc1.y = fmaf(v1.y, a1, acc1.y);
        acc1.z = fmaf(v1.z, a1, acc1.z); acc1.w = fmaf(v1.w, a1, acc1.w);
    }
    if (s < deg) {
        float4 v0 = *(const float4*)&xwb[ssrc[s]*1024 + col4];
        float a0 = salh[s];
        acc0.x = fmaf(v0.x, a0, acc0.x); acc0.y = fmaf(v0.y, a0, acc0.y);
        acc0.z = fmaf(v0.z, a0, acc0.z); acc0.w = fmaf(v0.w, a0, acc0.w);
    }
    float4 bia = *(const float4*)&gat1_b[col4];
    float4 oh;
    oh.x = fmaxf(acc0.x + acc1.x + bia.x, 0.f);
    oh.y = fmaxf(acc0.y + acc1.y + bia.y, 0.f);
    oh.z = fmaxf(acc0.z + acc1.z + bia.z, 0.f);
    oh.w = fmaxf(acc0.w + acc1.w + bia.w, 0.f);

    // ---- fused xw2 = h1 @ gat2_w  (block reduction) ----
    float4 w0 = *(const float4*)&gat2_w[col4*2];      // cols col4, col4+1 (ch0,ch1 interleaved)
    float4 w1 = *(const float4*)&gat2_w[col4*2 + 4];
    float c0 = oh.x*w0.x + oh.y*w0.z + oh.z*w1.x + oh.w*w1.z;
    float c1 = oh.x*w0.y + oh.y*w0.w + oh.z*w1.y + oh.w*w1.w;
    #pragma unroll
    for (int o = 16; o; o >>= 1) {
        c0 += __shfl_down_sync(0xffffffffu, c0, o);
        c1 += __shfl_down_sync(0xffffffffu, c1, o);
    }
    if (lane == 0) { red[warp][0] = c0; red[warp][1] = c1; }
    __syncthreads();
    if (tid == 0) {
        float s0 = 0.f, s1 = 0.f;
        #pragma unroll
        for (int w = 0; w < 8; w++) { s0 += red[w][0]; s1 += red[w][1]; }
        g_xw2[bn*2 + 0] = s0;
        g_xw2[bn*2 + 1] = s1;
        g_as2[bn] = s0*att_src2[0] + s1*att_src2[1];
        g_ad2[bn] = s0*att_dst2[0] + s1*att_dst2[1];
    }
}

// ---------------- GAT layer 2: softmax + warp-parallel aggregate -------------
__global__ __launch_bounds__(32) void k_gat2(const float* __restrict__ gat2_b,
                                             float* __restrict__ out)
{
    int bn = blockIdx.x; int b = bn / NN;
    __shared__ float sal[MAXDEG];
    __shared__ int   ssrc[MAXDEG];
    int lane = threadIdx.x;
    int deg = g_deg[bn];
    for (int s = lane; s < deg; s += 32) ssrc[s] = g_srcl[bn*MAXDEG + s];
    __syncwarp();
    float adv = g_ad2[bn];
    float m = -3.4e38f;
    for (int s = lane; s < deg; s += 32) {
        float e = g_as2[b*NN + ssrc[s]] + adv;
        e = (e >= 0.f) ? e : 0.2f*e;
        sal[s] = e;
        m = fmaxf(m, e);
    }
    #pragma unroll
    for (int o = 16; o; o >>= 1) m = fmaxf(m, __shfl_xor_sync(0xffffffffu, m, o));
    float sum = 0.f;
    for (int s = lane; s < deg; s += 32) {
        float ex = expf(sal[s] - m);
        sal[s] = ex;
        sum += ex;
    }
    #pragma unroll
    for (int o = 16; o; o >>= 1) sum += __shfl_xor_sync(0xffffffffu, sum, o);
    float inv = 1.f / fmaxf(sum, 1e-16f);
    __syncwarp();
    float a0 = 0.f, a1 = 0.f;
    for (int s = lane; s < deg; s += 32) {
        float w = sal[s] * inv;
        float2 xv = *(const float2*)&g_xw2[(b*NN + ssrc[s])*2];
        a0 = fmaf(xv.x, w, a0);
        a1 = fmaf(xv.y, w, a1);
    }
    #pragma unroll
    for (int o = 16; o; o >>= 1) {
        a0 += __shfl_down_sync(0xffffffffu, a0, o);
        a1 += __shfl_down_sync(0xffffffffu, a1, o);
    }
    if (lane == 0) {
        out[bn*2 + 0] = a0 + gat2_b[0];
        out[bn*2 + 1] = a1 + gat2_b[1];
    }
}

// ---------------- launch ------------------------------------------------------
extern "C" void kernel_launch(void* const* d_in, const int* in_sizes, int n_in,
                              void* d_out, int out_size)
{
    const float* feats   = (const float*)d_in[0];
    const float* boxes   = (const float*)d_in[1];
    const float* fc1_w   = (const float*)d_in[2];
    const float* fc1_b   = (const float*)d_in[3];
    const float* fc2_w   = (const float*)d_in[4];
    // d_in[5] = fc2_b : constant shift, irrelevant for top-k
    const float* gat1_w  = (const float*)d_in[6];
    const float* g1as    = (const float*)d_in[7];
    const float* g1ad    = (const float*)d_in[8];
    const float* gat1_b  = (const float*)d_in[9];
    const float* gat2_w  = (const float*)d_in[10];
    const float* g2as    = (const float*)d_in[11];
    const float* g2ad    = (const float*)d_in[12];
    const float* gat2_b  = (const float*)d_in[13];
    float* out = (float*)d_out;

    k_gemms   <<<144, 256>>>(feats, fc1_w, gat1_w, boxes);
    k_rel_asad<<<192 + BB*NN, 256>>>(boxes, fc1_w, fc1_b, fc2_w, g1as, g1ad);
    k_gat1    <<<BB*NN, 256>>>(gat1_b, gat2_w, g2as, g2ad);
    k_gat2    <<<BB*NN, 32>>>(gat2_b, out);
    (void)in_sizes; (void)n_in; (void)out_size;
}

// round 6
// speedup vs baseline: 2.2764x; 1.0485x over previous
#include <cuda_runtime.h>
#include <math.h>

#define BB 2
#define NN 384
#define CC 1024
#define HREPN 256
#define GHID 256
#define NHEADS 4
#define TOPKK 8
#define MAXDEG 400

typedef unsigned long long ull;

// ---------------- scratch (device globals; no allocation allowed) ------------
__device__ __align__(16) float g_p1 [BB*NN*HREPN];
__device__ __align__(16) float g_p2 [BB*NN*HREPN];
__device__ __align__(16) float g_xw1[BB*NN*NHEADS*GHID];
__device__ float g_as1[BB*NN*NHEADS];
__device__ float g_ad1[BB*NN*NHEADS];
__device__ int   g_nbr[BB*NN*TOPKK];
__device__ int   g_srcl[BB*NN*MAXDEG];
__device__ int   g_deg [BB*NN];
__device__ float g_xw2[BB*NN*2];
__device__ float g_as2[BB*NN];
__device__ float g_ad2[BB*NN];

// ---------------- f32x2 helpers (only add/mul/fma exist in PTX) --------------
__device__ __forceinline__ void ffma2(ull &d, ull a, ull b) {
    asm("fma.rn.f32x2 %0, %1, %2, %0;" : "+l"(d) : "l"(a), "l"(b));
}
__device__ __forceinline__ ull fma2v(ull a, ull b, ull c) {
    ull r; asm("fma.rn.f32x2 %0, %1, %2, %3;" : "=l"(r) : "l"(a), "l"(b), "l"(c)); return r;
}
__device__ __forceinline__ ull add2v(ull a, ull b) {
    ull r; asm("add.rn.f32x2 %0, %1, %2;" : "=l"(r) : "l"(a), "l"(b)); return r;
}
__device__ __forceinline__ ull pack2(float lo, float hi) {
    ull r; asm("mov.b64 %0, {%1, %2};" : "=l"(r) : "f"(lo), "f"(hi)); return r;
}
__device__ __forceinline__ void unpack2(ull v, float &lo, float &hi) {
    asm("mov.b64 {%0, %1}, %2;" : "=f"(lo), "=f"(hi) : "l"(v));
}
__device__ __forceinline__ float lo2(ull v) { return __uint_as_float((unsigned)(v & 0xffffffffull)); }
__device__ __forceinline__ float hi2(ull v) { return __uint_as_float((unsigned)(v >> 32)); }

// ---------------- fused SGEMM: 128x64 tiles, 128 thr, 8x8 blocking -----------
// LDS/FFMA2 balanced: 1.0 B/FMA. rows = ty + 16r, cols = tx + 8j (bank-clean).
__global__ __launch_bounds__(128, 1) void k_gemms(
    const float* __restrict__ feats,
    const float* __restrict__ fc1_w,
    const float* __restrict__ gat1_w,
    const float* __restrict__ boxes)
{
    __shared__ float As[2][128*20];   // [row][k], ld=20
    __shared__ float Bs[2][64*20];    // [col][k], ld=20
    __shared__ float Wg4[4*64];

    int tid = threadIdx.x;
    int bid = blockIdx.x;
    int sel, b, by, bx;
    if (bid < 48) { sel = 0; b = bid / 24; int r = bid % 24; by = r / 8;  bx = r % 8;  }
    else { sel = 1; int r = bid - 48; b = r / 48; r %= 48;   by = r / 16; bx = r % 16; }

    int row0 = by * 128, col0 = bx * 64;

    const float* A = feats + b*NN*CC;
    const float* Bm; float* Cm;
    int ldb, Nc, dcol0;
    if (sel == 0) {
        ldb = 256; Nc = 256;
        if (col0 < 256) { Bm = fc1_w;            Cm = g_p1 + b*NN*256; dcol0 = col0; }
        else            { Bm = fc1_w + 1024*256; Cm = g_p2 + b*NN*256; dcol0 = col0 - 256; }
    } else {
        ldb = 1024; Nc = 1024; Bm = gat1_w; Cm = g_xw1 + b*NN*1024; dcol0 = col0;
        Wg4[tid]       = gat1_w[(1024 + (tid >> 6))*1024 + col0 + (tid & 63)];
        Wg4[tid + 128] = gat1_w[(1026 + (tid >> 6))*1024 + col0 + (tid & 63)];
    }

    int tx = tid & 7, ty = tid >> 3;     // 8 x 16 thread grid
    ull acc[8][8];
    #pragma unroll
    for (int r = 0; r < 8; r++)
        #pragma unroll
        for (int j = 0; j < 8; j++) acc[r][j] = 0ull;

    int arow = tid >> 2, aslot = tid & 3;   // A loader: rows arow+32m, float4 slot aslot
    int bc = tid & 63, bk = tid >> 6;       // B loader: col bc, k's bk*8..+7

    const float* ApB = A + (row0 + arow)*1024 + aslot*4;
    const float* Bp  = Bm + dcol0 + bc;

    float4 pa[4]; float pb[8];
    // prologue: fetch tile 0
    #pragma unroll
    for (int m = 0; m < 4; m++) pa[m] = *(const float4*)(ApB + m*32*1024);
    #pragma unroll
    for (int m = 0; m < 8; m++) pb[m] = Bp[(bk*8 + m)*ldb];
    #pragma unroll
    for (int m = 0; m < 4; m++) *(float4*)&As[0][(arow + 32*m)*20 + aslot*4] = pa[m];
    #pragma unroll
    for (int m = 0; m < 8; m++) Bs[0][bc*20 + bk*8 + m] = pb[m];
    __syncthreads();

    for (int t = 0; t < 64; t++) {
        int cur = t & 1, nxt = cur ^ 1;
        if (t < 63) {
            int k0 = (t + 1) * 16;
            #pragma unroll
            for (int m = 0; m < 4; m++) pa[m] = *(const float4*)(ApB + m*32*1024 + k0);
            #pragma unroll
            for (int m = 0; m < 8; m++) pb[m] = Bp[(k0 + bk*8 + m)*ldb];
        }
        #pragma unroll
        for (int kp = 0; kp < 8; kp++) {
            ull av[8], bv[8];
            #pragma unroll
            for (int r = 0; r < 8; r++)
                av[r] = *(const ull*)&As[cur][(ty + 16*r)*20 + 2*kp];
            #pragma unroll
            for (int j = 0; j < 8; j++)
                bv[j] = *(const ull*)&Bs[cur][(tx + 8*j)*20 + 2*kp];
            #pragma unroll
            for (int r = 0; r < 8; r++)
                #pragma unroll
                for (int j = 0; j < 8; j++) ffma2(acc[r][j], av[r], bv[j]);
        }
        if (t < 63) {
            #pragma unroll
            for (int m = 0; m < 4; m++) *(float4*)&As[nxt][(arow + 32*m)*20 + aslot*4] = pa[m];
            #pragma unroll
            for (int m = 0; m < 8; m++) Bs[nxt][bc*20 + bk*8 + m] = pb[m];
        }
        __syncthreads();
    }

    #pragma unroll
    for (int r = 0; r < 8; r++) {
        int row = row0 + ty + 16*r;
        float g0 = 0.f, g1 = 0.f, g2 = 0.f, g3 = 0.f;
        if (sel == 1) {
            const float* bx4 = boxes + (b*NN + row)*4;
            float x0 = bx4[0]*(1.0f/800.0f), y0 = bx4[1]*(1.0f/800.0f);
            float x1 = bx4[2]*(1.0f/800.0f), y1 = bx4[3]*(1.0f/800.0f);
            g0 = x0; g1 = y0; g2 = x1 - x0; g3 = y1 - y0;
        }
        #pragma unroll
        for (int j = 0; j < 8; j++) {
            int c = tx + 8*j;
            float s = lo2(acc[r][j]) + hi2(acc[r][j]);
            if (sel == 1) {
                s = fmaf(g0, Wg4[0*64 + c], s);
                s = fmaf(g1, Wg4[1*64 + c], s);
                s = fmaf(g2, Wg4[2*64 + c], s);
                s = fmaf(g3, Wg4[3*64 + c], s);
            }
            Cm[row*Nc + dcol0 + c] = s;
        }
    }
}

// ------- merged: relation scores + top-8 (blocks 0..191)  |  asad (192..575) -
__global__ __launch_bounds__(256) void k_rel_asad(
    const float* __restrict__ boxes,
    const float* __restrict__ fc1_w,
    const float* __restrict__ fc1_b,
    const float* __restrict__ fc2_w,
    const float* __restrict__ att_src,
    const float* __restrict__ att_dst)
{
    __shared__ float srow[4][NN];
    __shared__ float sbx[16];
    int bid = blockIdx.x;
    int tid = threadIdx.x, warp = tid >> 5, lane = tid & 31;

    if (bid >= 192) {
        // ---- asad role: 2 nodes per block, warp (tid>>5)&3 == head ----
        int bn = (bid - 192)*2 + (tid >> 7);
        int h = (tid >> 5) & 3;
        const float* xw = g_xw1 + bn*1024 + h*256 + lane*8;
        float4 v0 = *(const float4*)xw;
        float4 v1 = *(const float4*)(xw + 4);
        const float* asr = att_src + h*256 + lane*8;
        const float* adr = att_dst + h*256 + lane*8;
        float4 s0 = *(const float4*)asr;
        float4 s1 = *(const float4*)(asr + 4);
        float4 d0 = *(const float4*)adr;
        float4 d1 = *(const float4*)(adr + 4);
        float ss = v0.x*s0.x + v0.y*s0.y + v0.z*s0.z + v0.w*s0.w
                 + v1.x*s1.x + v1.y*s1.y + v1.z*s1.z + v1.w*s1.w;
        float dd = v0.x*d0.x + v0.y*d0.y + v0.z*d0.z + v0.w*d0.w
                 + v1.x*d1.x + v1.y*d1.y + v1.z*d1.z + v1.w*d1.w;
        #pragma unroll
        for (int o = 16; o; o >>= 1) {
            ss += __shfl_down_sync(0xffffffffu, ss, o);
            dd += __shfl_down_sync(0xffffffffu, dd, o);
        }
        if (lane == 0) { g_as1[bn*4 + h] = ss; g_ad1[bn*4 + h] = dd; }
        return;
    }

    // ---- rel_topk role ----
    int b = bid / 96, igrp = bid % 96;
    int i0 = igrp * 4;

    if (tid < 16) sbx[tid] = boxes[(b*NN + i0 + (tid >> 2))*4 + (tid & 3)];

    ull wg2[4][4], sp1q[4][4];
    float w2lo[4], w2hi[4];
    #pragma unroll
    for (int p = 0; p < 4; p++) {
        int k0 = lane + 64*p, k1 = k0 + 32;
        w2lo[p] = fc2_w[k0];
        w2hi[p] = fc2_w[k1];
        #pragma unroll
        for (int d = 0; d < 4; d++)
            wg2[d][p] = pack2(fc1_w[(2048+d)*256 + k0], fc1_w[(2048+d)*256 + k1]);
        float b0 = fc1_b[k0], b1 = fc1_b[k1];
        #pragma unroll
        for (int q = 0; q < 4; q++) {
            const float* p1r = g_p1 + (b*NN + i0 + q)*256;
            sp1q[q][p] = pack2(p1r[k0] + b0, p1r[k1] + b1);
        }
    }
    __syncthreads();

    const float* p2b = g_p2 + b*NN*256;
    const float* bxb = boxes + b*NN*4;

    for (int j = warp; j < NN; j += 8) {
        float4 bj = *(const float4*)&bxb[j*4];
        ull p2v[4];
        #pragma unroll
        for (int p = 0; p < 4; p++) {
            int k0 = lane + 64*p;
            p2v[p] = pack2(p2b[j*256 + k0], p2b[j*256 + k0 + 32]);
        }
        #pragma unroll
        for (int q = 0; q < 4; q++) {
            float d0 = fabsf(sbx[q*4+0] - bj.x);
            float d1 = fabsf(sbx[q*4+1] - bj.y);
            float d2 = fabsf(sbx[q*4+2] - bj.z);
            float d3 = fabsf(sbx[q*4+3] - bj.w);
            ull a0 = pack2(d0, d0), a1 = pack2(d1, d1);
            ull a2 = pack2(d2, d2), a3 = pack2(d3, d3);
            float sum = 0.f;
            #pragma unroll
            for (int p = 0; p < 4; p++) {
                ull t = add2v(sp1q[q][p], p2v[p]);
                t = fma2v(a0, wg2[0][p], t);
                t = fma2v(a1, wg2[1][p], t);
                t = fma2v(a2, wg2[2][p], t);
                t = fma2v(a3, wg2[3][p], t);
                float tl, th;
                unpack2(t, tl, th);
                tl = fmaxf(tl, 0.f);
                th = fmaxf(th, 0.f);
                sum = fmaf(tl, w2lo[p], sum);
                sum = fmaf(th, w2hi[p], sum);
            }
            #pragma unroll
            for (int o = 16; o; o >>= 1) sum += __shfl_down_sync(0xffffffffu, sum, o);
            if (lane == 0)
                srow[q][j] = sum - ((j == i0 + q) ? 1e6f : 0.f);
        }
    }
    __syncthreads();

    if (warp < 4) {
        int q = warp, i = i0 + q;
        for (int sel = 0; sel < TOPKK; sel++) {
            float bv = -3.4e38f; int bi = 1 << 30;
            for (int j = lane; j < NN; j += 32) {
                float v = srow[q][j];
                if (v > bv || (v == bv && j < bi)) { bv = v; bi = j; }
            }
            #pragma unroll
            for (int o = 16; o; o >>= 1) {
                float ov = __shfl_xor_sync(0xffffffffu, bv, o);
                int   oi = __shfl_xor_sync(0xffffffffu, bi, o);
                if (ov > bv || (ov == bv && oi < bi)) { bv = ov; bi = oi; }
            }
            if (lane == 0) {
                g_nbr[(b*NN + i)*TOPKK + sel] = bi;
                srow[q][bi] = -3.4e38f;
            }
            __syncwarp();
        }
    }
}

// -------- GAT1: fused edge-build + softmax + float4 aggregate + xw2 ----------
__global__ __launch_bounds__(256) void k_gat1(
    const float* __restrict__ gat1_b,
    const float* __restrict__ gat2_w,
    const float* __restrict__ att_src2,
    const float* __restrict__ att_dst2)
{
    int bn = blockIdx.x; int b = bn / NN, tt = bn % NN;
    __shared__ int   ssrc[MAXDEG];
    __shared__ float sal[NHEADS][MAXDEG];
    __shared__ int   scnt[256];
    __shared__ float red[8][2];
    __shared__ int   sdeg;
    int tid = threadIdx.x;

    // ---- build phase: deterministic incoming-edge list for target tt ----
    const int* nb = g_nbr + b*NN*TOPKK;
    int myc0 = 0, myc1 = 0;
    int ia = 2*tid, ib = 2*tid + 1;
    if (tid < 192) {
        #pragma unroll
        for (int k = 0; k < TOPKK; k++) {
            myc0 += (nb[ia*TOPKK + k] == tt);
            myc1 += (nb[ib*TOPKK + k] == tt);
        }
    }
    int tot = myc0 + myc1;
    scnt[tid] = tot;
    __syncthreads();
    for (int s = 1; s < 256; s <<= 1) {
        int v = (tid >= s) ? scnt[tid - s] : 0;
        __syncthreads();
        scnt[tid] += v;
        __syncthreads();
    }
    int off = scnt[tid] - tot;
    int* dst = g_srcl + bn*MAXDEG;
    if (tid < 192) {
        if (myc0) {
            #pragma unroll
            for (int k = 0; k < TOPKK; k++)
                if (nb[ia*TOPKK + k] == tt) { ssrc[off] = ia; dst[off] = ia; off++; }
        }
        if (myc1) {
            #pragma unroll
            for (int k = 0; k < TOPKK; k++)
                if (nb[ib*TOPKK + k] == tt) { ssrc[off] = ib; dst[off] = ib; off++; }
        }
    }
    if (tid == 255) {
        int total = scnt[255];
        ssrc[total] = tt;
        dst[total] = tt;
        g_deg[bn] = total + 1;
        sdeg = total + 1;
    }
    __syncthreads();
    int deg = sdeg;

    // ---- softmax phase (warp h handles head h) ----
    int warp = tid >> 5, lane = tid & 31;
    if (warp < NHEADS) {
        int h = warp;
        float adv = g_ad1[bn*4 + h];
        float m = -3.4e38f;
        for (int s = lane; s < deg; s += 32) {
            float e = g_as1[(b*NN + ssrc[s])*4 + h] + adv;
            e = (e >= 0.f) ? e : 0.2f*e;
            sal[h][s] = e;
            m = fmaxf(m, e);
        }
        #pragma unroll
        for (int o = 16; o; o >>= 1) m = fmaxf(m, __shfl_xor_sync(0xffffffffu, m, o));
        float sum = 0.f;
        for (int s = lane; s < deg; s += 32) {
            float ex = expf(sal[h][s] - m);
            sal[h][s] = ex;
            sum += ex;
        }
        #pragma unroll
        for (int o = 16; o; o >>= 1) sum += __shfl_xor_sync(0xffffffffu, sum, o);
        float inv = 1.f / fmaxf(sum, 1e-16f);
        for (int s = lane; s < deg; s += 32) sal[h][s] *= inv;
    }
    __syncthreads();

    // ---- aggregate: thread owns 4 contiguous cols (float4), h = tid>>6 ----
    const float* xwb = g_xw1 + b*NN*1024;
    const float* salh = sal[tid >> 6];
    float4 acc0 = make_float4(0.f, 0.f, 0.f, 0.f);
    float4 acc1 = make_float4(0.f, 0.f, 0.f, 0.f);
    int col4 = tid * 4;
    int s = 0;
    for (; s + 1 < deg; s += 2) {
        float4 v0 = *(const float4*)&xwb[ssrc[s  ]*1024 + col4];
        float4 v1 = *(const float4*)&xwb[ssrc[s+1]*1024 + col4];
        float a0 = salh[s], a1 = salh[s+1];
        acc0.x = fmaf(v0.x, a0, acc0.x); acc0.y = fmaf(v0.y, a0, acc0.y);
        acc0.z = fmaf(v0.z, a0, acc0.z); acc0.w = fmaf(v0.w, a0, acc0.w);
        acc1.x = fmaf(v1.x, a1, acc1.x); acc1.y = fmaf(v1.y, a1, acc1.y);
        acc1.z = fmaf(v1.z, a1, acc1.z); acc1.w = fmaf(v1.w, a1, acc1.w);
    }
    if (s < deg) {
        float4 v0 = *(const float4*)&xwb[ssrc[s]*1024 + col4];
        float a0 = salh[s];
        acc0.x = fmaf(v0.x, a0, acc0.x); acc0.y = fmaf(v0.y, a0, acc0.y);
        acc0.z = fmaf(v0.z, a0, acc0.z); acc0.w = fmaf(v0.w, a0, acc0.w);
    }
    float4 bia = *(const float4*)&gat1_b[col4];
    float4 oh;
    oh.x = fmaxf(acc0.x + acc1.x + bia.x, 0.f);
    oh.y = fmaxf(acc0.y + acc1.y + bia.y, 0.f);
    oh.z = fmaxf(acc0.z + acc1.z + bia.z, 0.f);
    oh.w = fmaxf(acc0.w + acc1.w + bia.w, 0.f);

    // ---- fused xw2 = h1 @ gat2_w  (block reduction) ----
    float4 w0 = *(const float4*)&gat2_w[col4*2];
    float4 w1 = *(const float4*)&gat2_w[col4*2 + 4];
    float c0 = oh.x*w0.x + oh.y*w0.z + oh.z*w1.x + oh.w*w1.z;
    float c1 = oh.x*w0.y + oh.y*w0.w + oh.z*w1.y + oh.w*w1.w;
    #pragma unroll
    for (int o = 16; o; o >>= 1) {
        c0 += __shfl_down_sync(0xffffffffu, c0, o);
        c1 += __shfl_down_sync(0xffffffffu, c1, o);
    }
    if (lane == 0) { red[warp][0] = c0; red[warp][1] = c1; }
    __syncthreads();
    if (tid == 0) {
        float s0 = 0.f, s1 = 0.f;
        #pragma unroll
        for (int w = 0; w < 8; w++) { s0 += red[w][0]; s1 += red[w][1]; }
        g_xw2[bn*2 + 0] = s0;
        g_xw2[bn*2 + 1] = s1;
        g_as2[bn] = s0*att_src2[0] + s1*att_src2[1];
        g_ad2[bn] = s0*att_dst2[0] + s1*att_dst2[1];
    }
}

// ------- GAT layer 2: 4 nodes per block, warp-per-node softmax+aggregate -----
__global__ __launch_bounds__(128) void k_gat2(const float* __restrict__ gat2_b,
                                              float* __restrict__ out)
{
    __shared__ float sal[4][MAXDEG];
    __shared__ int   ssrc[4][MAXDEG];
    int warp = threadIdx.x >> 5, lane = threadIdx.x & 31;
    int bn = blockIdx.x*4 + warp;
    int b = bn / NN;
    int deg = g_deg[bn];
    for (int s = lane; s < deg; s += 32) ssrc[warp][s] = g_srcl[bn*MAXDEG + s];
    __syncwarp();
    float adv = g_ad2[bn];
    float m = -3.4e38f;
    for (int s = lane; s < deg; s += 32) {
        float e = g_as2[b*NN + ssrc[warp][s]] + adv;
        e = (e >= 0.f) ? e : 0.2f*e;
        sal[warp][s] = e;
        m = fmaxf(m, e);
    }
    #pragma unroll
    for (int o = 16; o; o >>= 1) m = fmaxf(m, __shfl_xor_sync(0xffffffffu, m, o));
    float sum = 0.f;
    for (int s = lane; s < deg; s += 32) {
        float ex = expf(sal[warp][s] - m);
        sal[warp][s] = ex;
        sum += ex;
    }
    #pragma unroll
    for (int o = 16; o; o >>= 1) sum += __shfl_xor_sync(0xffffffffu, sum, o);
    float inv = 1.f / fmaxf(sum, 1e-16f);
    __syncwarp();
    float a0 = 0.f, a1 = 0.f;
    for (int s = lane; s < deg; s += 32) {
        float w = sal[warp][s] * inv;
        float2 xv = *(const float2*)&g_xw2[(b*NN + ssrc[warp][s])*2];
        a0 = fmaf(xv.x, w, a0);
        a1 = fmaf(xv.y, w, a1);
    }
    #pragma unroll
    for (int o = 16; o; o >>= 1) {
        a0 += __shfl_down_sync(0xffffffffu, a0, o);
        a1 += __shfl_down_sync(0xffffffffu, a1, o);
    }
    if (lane == 0) {
        out[bn*2 + 0] = a0 + gat2_b[0];
        out[bn*2 + 1] = a1 + gat2_b[1];
    }
}

// ---------------- launch ------------------------------------------------------
extern "C" void kernel_launch(void* const* d_in, const int* in_sizes, int n_in,
                              void* d_out, int out_size)
{
    const float* feats   = (const float*)d_in[0];
    const float* boxes   = (const float*)d_in[1];
    const float* fc1_w   = (const float*)d_in[2];
    const float* fc1_b   = (const float*)d_in[3];
    const float* fc2_w   = (const float*)d_in[4];
    // d_in[5] = fc2_b : constant shift, irrelevant for top-k
    const float* gat1_w  = (const float*)d_in[6];
    const float* g1as    = (const float*)d_in[7];
    const float* g1ad    = (const float*)d_in[8];
    const float* gat1_b  = (const float*)d_in[9];
    const float* gat2_w  = (const float*)d_in[10];
    const float* g2as    = (const float*)d_in[11];
    const float* g2ad    = (const float*)d_in[12];
    const float* gat2_b  = (const float*)d_in[13];
    float* out = (float*)d_out;

    k_gemms   <<<144, 128>>>(feats, fc1_w, gat1_w, boxes);
    k_rel_asad<<<192 + 384, 256>>>(boxes, fc1_w, fc1_b, fc2_w, g1as, g1ad);
    k_gat1    <<<BB*NN, 256>>>(gat1_b, gat2_w, g2as, g2ad);
    k_gat2    <<<192, 128>>>(gat2_b, out);
    (void)in_sizes; (void)n_in; (void)out_size;
}

// round 7
// speedup vs baseline: 2.4496x; 1.0761x over previous
#include <cuda_runtime.h>
#include <math.h>

#define BB 2
#define NN 384
#define CC 1024
#define HREPN 256
#define GHID 256
#define NHEADS 4
#define TOPKK 8
#define MAXDEG 400

typedef unsigned long long ull;

// ---------------- scratch (device globals; no allocation allowed) ------------
__device__ __align__(16) float g_p1 [BB*NN*HREPN];
__device__ __align__(16) float g_p2 [BB*NN*HREPN];
__device__ __align__(16) float g_xw1[BB*NN*NHEADS*GHID];
__device__ float g_as1[BB*NN*NHEADS];
__device__ float g_ad1[BB*NN*NHEADS];
__device__ int   g_nbr[BB*NN*TOPKK];
__device__ int   g_srcl[BB*NN*MAXDEG];
__device__ int   g_deg [BB*NN];
__device__ float g_xw2[BB*NN*2];
__device__ float g_as2[BB*NN];
__device__ float g_ad2[BB*NN];

// ---------------- f32x2 helpers (only add/mul/fma exist in PTX) --------------
__device__ __forceinline__ void ffma2(ull &d, ull a, ull b) {
    asm("fma.rn.f32x2 %0, %1, %2, %0;" : "+l"(d) : "l"(a), "l"(b));
}
__device__ __forceinline__ ull fma2v(ull a, ull b, ull c) {
    ull r; asm("fma.rn.f32x2 %0, %1, %2, %3;" : "=l"(r) : "l"(a), "l"(b), "l"(c)); return r;
}
__device__ __forceinline__ ull add2v(ull a, ull b) {
    ull r; asm("add.rn.f32x2 %0, %1, %2;" : "=l"(r) : "l"(a), "l"(b)); return r;
}
__device__ __forceinline__ ull pack2(float lo, float hi) {
    ull r; asm("mov.b64 %0, {%1, %2};" : "=l"(r) : "f"(lo), "f"(hi)); return r;
}
__device__ __forceinline__ void unpack2(ull v, float &lo, float &hi) {
    asm("mov.b64 {%0, %1}, %2;" : "=f"(lo), "=f"(hi) : "l"(v));
}
__device__ __forceinline__ float lo2(ull v) { return __uint_as_float((unsigned)(v & 0xffffffffull)); }
__device__ __forceinline__ float hi2(ull v) { return __uint_as_float((unsigned)(v >> 32)); }

// -------- fused SGEMM: 128x64 tiles, 256 thr, intra-block K-split ------------
// Half A (tid<128): K[0:512].  Half B: K[512:1024].  Each half: 8x8 FFMA2
// blocking with its own double-buffered smem.  Combine via padded smem.
__global__ __launch_bounds__(256, 1) void k_gemms(
    const float* __restrict__ feats,
    const float* __restrict__ fc1_w,
    const float* __restrict__ gat1_w,
    const float* __restrict__ boxes)
{
    __shared__ float As[2][2][128*20];   // [khalf][buf][row*20+k]
    __shared__ float Bs[2][2][64*20];    // [khalf][buf][col*20+k]
    __shared__ float Wg4[4*64];

    int tid = threadIdx.x;
    int khalf = tid >> 7;          // 0 or 1
    int htid  = tid & 127;
    int bid = blockIdx.x;
    int sel, b, by, bx;
    if (bid < 48) { sel = 0; b = bid / 24; int r = bid % 24; by = r / 8;  bx = r % 8;  }
    else { sel = 1; int r = bid - 48; b = r / 48; r %= 48;   by = r / 16; bx = r % 16; }

    int row0 = by * 128, col0 = bx * 64;

    const float* A = feats + b*NN*CC;
    const float* Bm; float* Cm;
    int ldb, Nc, dcol0;
    if (sel == 0) {
        ldb = 256; Nc = 256;
        if (col0 < 256) { Bm = fc1_w;            Cm = g_p1 + b*NN*256; dcol0 = col0; }
        else            { Bm = fc1_w + 1024*256; Cm = g_p2 + b*NN*256; dcol0 = col0 - 256; }
    } else {
        ldb = 1024; Nc = 1024; Bm = gat1_w; Cm = g_xw1 + b*NN*1024; dcol0 = col0;
        Wg4[tid] = gat1_w[(1024 + (tid >> 6))*1024 + col0 + (tid & 63)];
    }

    int tx = htid & 7, ty = htid >> 3;      // 8 x 16 thread grid per half
    ull acc[8][8];
    #pragma unroll
    for (int r = 0; r < 8; r++)
        #pragma unroll
        for (int j = 0; j < 8; j++) acc[r][j] = 0ull;

    int arow = htid >> 2, aslot = htid & 3;   // A loader: rows arow+32m
    int bc = htid & 63, bk = htid >> 6;       // B loader: col bc, k's bk*8..+7

    int kbase = khalf * 512;
    const float* ApB = A + (row0 + arow)*1024 + kbase + aslot*4;
    const float* Bp  = Bm + (ull)kbase*ldb + dcol0 + bc;

    float4 pa[4]; float pb[8];
    #pragma unroll
    for (int m = 0; m < 4; m++) pa[m] = *(const float4*)(ApB + m*32*1024);
    #pragma unroll
    for (int m = 0; m < 8; m++) pb[m] = Bp[(bk*8 + m)*ldb];
    #pragma unroll
    for (int m = 0; m < 4; m++) *(float4*)&As[khalf][0][(arow + 32*m)*20 + aslot*4] = pa[m];
    #pragma unroll
    for (int m = 0; m < 8; m++) Bs[khalf][0][bc*20 + bk*8 + m] = pb[m];
    __syncthreads();

    for (int t = 0; t < 32; t++) {
        int cur = t & 1, nxt = cur ^ 1;
        if (t < 31) {
            int k0 = (t + 1) * 16;
            #pragma unroll
            for (int m = 0; m < 4; m++) pa[m] = *(const float4*)(ApB + m*32*1024 + k0);
            #pragma unroll
            for (int m = 0; m < 8; m++) pb[m] = Bp[(k0 + bk*8 + m)*ldb];
        }
        #pragma unroll
        for (int kp = 0; kp < 8; kp++) {
            ull av[8], bv[8];
            #pragma unroll
            for (int r = 0; r < 8; r++)
                av[r] = *(const ull*)&As[khalf][cur][(ty + 16*r)*20 + 2*kp];
            #pragma unroll
            for (int j = 0; j < 8; j++)
                bv[j] = *(const ull*)&Bs[khalf][cur][(tx + 8*j)*20 + 2*kp];
            #pragma unroll
            for (int r = 0; r < 8; r++)
                #pragma unroll
                for (int j = 0; j < 8; j++) ffma2(acc[r][j], av[r], bv[j]);
        }
        if (t < 31) {
            #pragma unroll
            for (int m = 0; m < 4; m++) *(float4*)&As[khalf][nxt][(arow + 32*m)*20 + aslot*4] = pa[m];
            #pragma unroll
            for (int m = 0; m < 8; m++) Bs[khalf][nxt][bc*20 + bk*8 + m] = pb[m];
        }
        __syncthreads();
    }

    // ---- combine halves via padded smem (stride 65: bank-conflict-free) ----
    float* comb = (float*)As;     // 128*65 floats = 33.3KB < As (40KB)
    if (khalf == 1) {
        #pragma unroll
        for (int r = 0; r < 8; r++)
            #pragma unroll
            for (int j = 0; j < 8; j++)
                comb[htid*65 + r*8 + j] = lo2(acc[r][j]) + hi2(acc[r][j]);
    }
    __syncthreads();
    if (khalf == 0) {
        #pragma unroll
        for (int r = 0; r < 8; r++) {
            int row = row0 + ty + 16*r;
            float g0 = 0.f, g1 = 0.f, g2 = 0.f, g3 = 0.f;
            if (sel == 1) {
                const float* bx4 = boxes + (b*NN + row)*4;
                float x0 = bx4[0]*(1.0f/800.0f), y0 = bx4[1]*(1.0f/800.0f);
                float x1 = bx4[2]*(1.0f/800.0f), y1 = bx4[3]*(1.0f/800.0f);
                g0 = x0; g1 = y0; g2 = x1 - x0; g3 = y1 - y0;
            }
            #pragma unroll
            for (int j = 0; j < 8; j++) {
                int c = tx + 8*j;
                float s = (lo2(acc[r][j]) + hi2(acc[r][j])) + comb[htid*65 + r*8 + j];
                if (sel == 1) {
                    s = fmaf(g0, Wg4[0*64 + c], s);
                    s = fmaf(g1, Wg4[1*64 + c], s);
                    s = fmaf(g2, Wg4[2*64 + c], s);
                    s = fmaf(g3, Wg4[3*64 + c], s);
                }
                Cm[row*Nc + dcol0 + c] = s;
            }
        }
    }
}

// ------- merged: relation scores + top-8 (blocks 0..191)  |  asad (192..575) -
__global__ __launch_bounds__(256) void k_rel_asad(
    const float* __restrict__ boxes,
    const float* __restrict__ fc1_w,
    const float* __restrict__ fc1_b,
    const float* __restrict__ fc2_w,
    const float* __restrict__ att_src,
    const float* __restrict__ att_dst)
{
    __shared__ float srow[4][NN];
    __shared__ float sbx[16];
    int bid = blockIdx.x;
    int tid = threadIdx.x, warp = tid >> 5, lane = tid & 31;

    if (bid >= 192) {
        // ---- asad role: 2 nodes per block, warp (tid>>5)&3 == head ----
        int bn = (bid - 192)*2 + (tid >> 7);
        int h = (tid >> 5) & 3;
        const float* xw = g_xw1 + bn*1024 + h*256 + lane*8;
        float4 v0 = *(const float4*)xw;
        float4 v1 = *(const float4*)(xw + 4);
        const float* asr = att_src + h*256 + lane*8;
        const float* adr = att_dst + h*256 + lane*8;
        float4 s0 = *(const float4*)asr;
        float4 s1 = *(const float4*)(asr + 4);
        float4 d0 = *(const float4*)adr;
        float4 d1 = *(const float4*)(adr + 4);
        float ss = v0.x*s0.x + v0.y*s0.y + v0.z*s0.z + v0.w*s0.w
                 + v1.x*s1.x + v1.y*s1.y + v1.z*s1.z + v1.w*s1.w;
        float dd = v0.x*d0.x + v0.y*d0.y + v0.z*d0.z + v0.w*d0.w
                 + v1.x*d1.x + v1.y*d1.y + v1.z*d1.z + v1.w*d1.w;
        #pragma unroll
        for (int o = 16; o; o >>= 1) {
            ss += __shfl_down_sync(0xffffffffu, ss, o);
            dd += __shfl_down_sync(0xffffffffu, dd, o);
        }
        if (lane == 0) { g_as1[bn*4 + h] = ss; g_ad1[bn*4 + h] = dd; }
        return;
    }

    // ---- rel_topk role ----
    int b = bid / 96, igrp = bid % 96;
    int i0 = igrp * 4;

    if (tid < 16) sbx[tid] = boxes[(b*NN + i0 + (tid >> 2))*4 + (tid & 3)];

    ull wg2[4][4], sp1q[4][4];
    float w2lo[4], w2hi[4];
    #pragma unroll
    for (int p = 0; p < 4; p++) {
        int k0 = lane + 64*p, k1 = k0 + 32;
        w2lo[p] = fc2_w[k0];
        w2hi[p] = fc2_w[k1];
        #pragma unroll
        for (int d = 0; d < 4; d++)
            wg2[d][p] = pack2(fc1_w[(2048+d)*256 + k0], fc1_w[(2048+d)*256 + k1]);
        float b0 = fc1_b[k0], b1 = fc1_b[k1];
        #pragma unroll
        for (int q = 0; q < 4; q++) {
            const float* p1r = g_p1 + (b*NN + i0 + q)*256;
            sp1q[q][p] = pack2(p1r[k0] + b0, p1r[k1] + b1);
        }
    }
    __syncthreads();

    const float* p2b = g_p2 + b*NN*256;
    const float* bxb = boxes + b*NN*4;

    for (int j = warp; j < NN; j += 8) {
        float4 bj = *(const float4*)&bxb[j*4];
        ull p2v[4];
        #pragma unroll
        for (int p = 0; p < 4; p++) {
            int k0 = lane + 64*p;
            p2v[p] = pack2(p2b[j*256 + k0], p2b[j*256 + k0 + 32]);
        }
        #pragma unroll
        for (int q = 0; q < 4; q++) {
            float d0 = fabsf(sbx[q*4+0] - bj.x);
            float d1 = fabsf(sbx[q*4+1] - bj.y);
            float d2 = fabsf(sbx[q*4+2] - bj.z);
            float d3 = fabsf(sbx[q*4+3] - bj.w);
            ull a0 = pack2(d0, d0), a1 = pack2(d1, d1);
            ull a2 = pack2(d2, d2), a3 = pack2(d3, d3);
            float sum = 0.f;
            #pragma unroll
            for (int p = 0; p < 4; p++) {
                ull t = add2v(sp1q[q][p], p2v[p]);
                t = fma2v(a0, wg2[0][p], t);
                t = fma2v(a1, wg2[1][p], t);
                t = fma2v(a2, wg2[2][p], t);
                t = fma2v(a3, wg2[3][p], t);
                float tl, th;
                unpack2(t, tl, th);
                tl = fmaxf(tl, 0.f);
                th = fmaxf(th, 0.f);
                sum = fmaf(tl, w2lo[p], sum);
                sum = fmaf(th, w2hi[p], sum);
            }
            #pragma unroll
            for (int o = 16; o; o >>= 1) sum += __shfl_down_sync(0xffffffffu, sum, o);
            if (lane == 0)
                srow[q][j] = sum - ((j == i0 + q) ? 1e6f : 0.f);
        }
    }
    __syncthreads();

    if (warp < 4) {
        int q = warp, i = i0 + q;
        for (int sel = 0; sel < TOPKK; sel++) {
            float bv = -3.4e38f; int bi = 1 << 30;
            for (int j = lane; j < NN; j += 32) {
                float v = srow[q][j];
                if (v > bv || (v == bv && j < bi)) { bv = v; bi = j; }
            }
            #pragma unroll
            for (int o = 16; o; o >>= 1) {
                float ov = __shfl_xor_sync(0xffffffffu, bv, o);
                int   oi = __shfl_xor_sync(0xffffffffu, bi, o);
                if (ov > bv || (ov == bv && oi < bi)) { bv = ov; bi = oi; }
            }
            if (lane == 0) {
                g_nbr[(b*NN + i)*TOPKK + sel] = bi;
                srow[q][bi] = -3.4e38f;
            }
            __syncwarp();
        }
    }
}

// -------- GAT1: fused edge-build + softmax + float4 aggregate + xw2 ----------
__global__ __launch_bounds__(256) void k_gat1(
    const float* __restrict__ gat1_b,
    const float* __restrict__ gat2_w,
    const float* __restrict__ att_src2,
    const float* __restrict__ att_dst2)
{
    int bn = blockIdx.x; int b = bn / NN, tt = bn % NN;
    __shared__ int   ssrc[MAXDEG];
    __shared__ float sal[NHEADS][MAXDEG];
    __shared__ float sas1[NN*4];
    __shared__ int   scnt[256];
    __shared__ float red[8][2];
    __shared__ int   sdeg;
    int tid = threadIdx.x;

    // batch as1 preload (6KB) — removes scattered L2 gathers in softmax
    #pragma unroll
    for (int it = 0; it < 6; it++)
        sas1[tid + it*256] = g_as1[b*NN*4 + tid + it*256];

    // ---- build phase: deterministic incoming-edge list for target tt ----
    const int* nb = g_nbr + b*NN*TOPKK;
    int myc0 = 0, myc1 = 0;
    int ia = 2*tid, ib = 2*tid + 1;
    if (tid < 192) {
        #pragma unroll
        for (int k = 0; k < TOPKK; k++) {
            myc0 += (nb[ia*TOPKK + k] == tt);
            myc1 += (nb[ib*TOPKK + k] == tt);
        }
    }
    int tot = myc0 + myc1;
    scnt[tid] = tot;
    __syncthreads();
    for (int s = 1; s < 256; s <<= 1) {
        int v = (tid >= s) ? scnt[tid - s] : 0;
        __syncthreads();
        scnt[tid] += v;
        __syncthreads();
    }
    int off = scnt[tid] - tot;
    int* dst = g_srcl + bn*MAXDEG;
    if (tid < 192) {
        if (myc0) {
            #pragma unroll
            for (int k = 0; k < TOPKK; k++)
                if (nb[ia*TOPKK + k] == tt) { ssrc[off] = ia; dst[off] = ia; off++; }
        }
        if (myc1) {
            #pragma unroll
            for (int k = 0; k < TOPKK; k++)
                if (nb[ib*TOPKK + k] == tt) { ssrc[off] = ib; dst[off] = ib; off++; }
        }
    }
    if (tid == 255) {
        int total = scnt[255];
        ssrc[total] = tt;
        dst[total] = tt;
        g_deg[bn] = total + 1;
        sdeg = total + 1;
    }
    __syncthreads();
    int deg = sdeg;

    // ---- softmax phase (warp h handles head h; as1 from smem) ----
    int warp = tid >> 5, lane = tid & 31;
    if (warp < NHEADS) {
        int h = warp;
        float adv = g_ad1[bn*4 + h];
        float m = -3.4e38f;
        for (int s = lane; s < deg; s += 32) {
            float e = sas1[ssrc[s]*4 + h] + adv;
            e = (e >= 0.f) ? e : 0.2f*e;
            sal[h][s] = e;
            m = fmaxf(m, e);
        }
        #pragma unroll
        for (int o = 16; o; o >>= 1) m = fmaxf(m, __shfl_xor_sync(0xffffffffu, m, o));
        float sum = 0.f;
        for (int s = lane; s < deg; s += 32) {
            float ex = expf(sal[h][s] - m);
            sal[h][s] = ex;
            sum += ex;
        }
        #pragma unroll
        for (int o = 16; o; o >>= 1) sum += __shfl_xor_sync(0xffffffffu, sum, o);
        float inv = 1.f / fmaxf(sum, 1e-16f);
        for (int s = lane; s < deg; s += 32) sal[h][s] *= inv;
    }
    __syncthreads();

    // ---- aggregate: thread owns 4 contiguous cols (float4), h = tid>>6 ----
    const float* xwb = g_xw1 + b*NN*1024;
    const float* salh = sal[tid >> 6];
    float4 acc0 = make_float4(0.f, 0.f, 0.f, 0.f);
    float4 acc1 = make_float4(0.f, 0.f, 0.f, 0.f);
    int col4 = tid * 4;
    int s = 0;
    for (; s + 1 < deg; s += 2) {
        float4 v0 = *(const float4*)&xwb[ssrc[s  ]*1024 + col4];
        float4 v1 = *(const float4*)&xwb[ssrc[s+1]*1024 + col4];
        float a0 = salh[s], a1 = salh[s+1];
        acc0.x = fmaf(v0.x, a0, acc0.x); acc0.y = fmaf(v0.y, a0, acc0.y);
        acc0.z = fmaf(v0.z, a0, acc0.z); acc0.w = fmaf(v0.w, a0, acc0.w);
        acc1.x = fmaf(v1.x, a1, acc1.x); acc1.y = fmaf(v1.y, a1, acc1.y);
        acc1.z = fmaf(v1.z, a1, acc1.z); acc1.w = fmaf(v1.w, a1, acc1.w);
    }
    if (s < deg) {
        float4 v0 = *(const float4*)&xwb[ssrc[s]*1024 + col4];
        float a0 = salh[s];
        acc0.x = fmaf(v0.x, a0, acc0.x); acc0.y = fmaf(v0.y, a0, acc0.y);
        acc0.z = fmaf(v0.z, a0, acc0.z); acc0.w = fmaf(v0.w, a0, acc0.w);
    }
    float4 bia = *(const float4*)&gat1_b[col4];
    float4 oh;
    oh.x = fmaxf(acc0.x + acc1.x + bia.x, 0.f);
    oh.y = fmaxf(acc0.y + acc1.y + bia.y, 0.f);
    oh.z = fmaxf(acc0.z + acc1.z + bia.z, 0.f);
    oh.w = fmaxf(acc0.w + acc1.w + bia.w, 0.f);

    // ---- fused xw2 = h1 @ gat2_w  (block reduction) ----
    float4 w0 = *(const float4*)&gat2_w[col4*2];
    float4 w1 = *(const float4*)&gat2_w[col4*2 + 4];
    float c0 = oh.x*w0.x + oh.y*w0.z + oh.z*w1.x + oh.w*w1.z;
    float c1 = oh.x*w0.y + oh.y*w0.w + oh.z*w1.y + oh.w*w1.w;
    #pragma unroll
    for (int o = 16; o; o >>= 1) {
        c0 += __shfl_down_sync(0xffffffffu, c0, o);
        c1 += __shfl_down_sync(0xffffffffu, c1, o);
    }
    if (lane == 0) { red[warp][0] = c0; red[warp][1] = c1; }
    __syncthreads();
    if (tid == 0) {
        float s0 = 0.f, s1 = 0.f;
        #pragma unroll
        for (int w = 0; w < 8; w++) { s0 += red[w][0]; s1 += red[w][1]; }
        g_xw2[bn*2 + 0] = s0;
        g_xw2[bn*2 + 1] = s1;
        g_as2[bn] = s0*att_src2[0] + s1*att_src2[1];
        g_ad2[bn] = s0*att_dst2[0] + s1*att_dst2[1];
    }
}

// ------- GAT layer 2: 8 nodes/block, batch as2/xw2 preloaded into smem -------
__global__ __launch_bounds__(256) void k_gat2(const float* __restrict__ gat2_b,
                                              float* __restrict__ out)
{
    __shared__ float s_as2[NN];
    __shared__ float s_xw2[NN*2];
    __shared__ float sal[8][MAXDEG];
    __shared__ int   ssrc[8][MAXDEG];
    int tid = threadIdx.x;
    int warp = tid >> 5, lane = tid & 31;
    int n0 = blockIdx.x * 8;
    int b = n0 / NN;

    // batch preload (384 + 768 floats)
    if (tid < 128) s_as2[tid] = g_as2[b*NN + tid];
    else           s_as2[tid + 128] = g_as2[b*NN + tid + 128];
    if (tid < 128) s_as2[tid + 128 + 128 - 256] = s_as2[tid + 128 + 128 - 256]; // no-op filler
    for (int i = tid; i < NN; i += 256)   s_as2[i] = g_as2[b*NN + i];
    for (int i = tid; i < NN*2; i += 256) s_xw2[i] = g_xw2[b*NN*2 + i];
    __syncthreads();

    int bn = n0 + warp;
    int deg = g_deg[bn];
    for (int s = lane; s < deg; s += 32) ssrc[warp][s] = g_srcl[bn*MAXDEG + s];
    __syncwarp();
    float adv = g_ad2[bn];
    float m = -3.4e38f;
    for (int s = lane; s < deg; s += 32) {
        float e = s_as2[ssrc[warp][s]] + adv;
        e = (e >= 0.f) ? e : 0.2f*e;
        sal[warp][s] = e;
        m = fmaxf(m, e);
    }
    #pragma unroll
    for (int o = 16; o; o >>= 1) m = fmaxf(m, __shfl_xor_sync(0xffffffffu, m, o));
    float sum = 0.f;
    for (int s = lane; s < deg; s += 32) {
        float ex = expf(sal[warp][s] - m);
        sal[warp][s] = ex;
        sum += ex;
    }
    #pragma unroll
    for (int o = 16; o; o >>= 1) sum += __shfl_xor_sync(0xffffffffu, sum, o);
    float inv = 1.f / fmaxf(sum, 1e-16f);
    __syncwarp();
    float a0 = 0.f, a1 = 0.f;
    for (int s = lane; s < deg; s += 32) {
        float w = sal[warp][s] * inv;
        int sc = ssrc[warp][s];
        a0 = fmaf(s_xw2[sc*2 + 0], w, a0);
        a1 = fmaf(s_xw2[sc*2 + 1], w, a1);
    }
    #pragma unroll
    for (int o = 16; o; o >>= 1) {
        a0 += __shfl_down_sync(0xffffffffu, a0, o);
        a1 += __shfl_down_sync(0xffffffffu, a1, o);
    }
    if (lane == 0) {
        out[bn*2 + 0] = a0 + gat2_b[0];
        out[bn*2 + 1] = a1 + gat2_b[1];
    }
}

// ---------------- launch ------------------------------------------------------
extern "C" void kernel_launch(void* const* d_in, const int* in_sizes, int n_in,
                              void* d_out, int out_size)
{
    const float* feats   = (const float*)d_in[0];
    const float* boxes   = (const float*)d_in[1];
    const float* fc1_w   = (const float*)d_in[2];
    const float* fc1_b   = (const float*)d_in[3];
    const float* fc2_w   = (const float*)d_in[4];
    // d_in[5] = fc2_b : constant shift, irrelevant for top-k
    const float* gat1_w  = (const float*)d_in[6];
    const float* g1as    = (const float*)d_in[7];
    const float* g1ad    = (const float*)d_in[8];
    const float* gat1_b  = (const float*)d_in[9];
    const float* gat2_w  = (const float*)d_in[10];
    const float* g2as    = (const float*)d_in[11];
    const float* g2ad    = (const float*)d_in[12];
    const float* gat2_b  = (const float*)d_in[13];
    float* out = (float*)d_out;

    k_gemms   <<<144, 256>>>(feats, fc1_w, gat1_w, boxes);
    k_rel_asad<<<192 + 384, 256>>>(boxes, fc1_w, fc1_b, fc2_w, g1as, g1ad);
    k_gat1    <<<BB*NN, 256>>>(gat1_b, gat2_w, g2as, g2ad);
    k_gat2    <<<96, 256>>>(gat2_b, out);
    (void)in_sizes; (void)n_in; (void)out_size;
}